// round 6
// baseline (speedup 1.0000x reference)
#include <cuda_runtime.h>
#include <cstdint>

#define MAXB  1024
#define EPS   1e-5f
#define SLOPE 0.01f

// ---------------- static device scratch (no allocations allowed) ----------------
__device__ __align__(16) float d_A [MAXB * 128];  // per-graph sum of a_e
__device__ __align__(16) float d_gx[MAXB * 64];   // per-graph sum of x
__device__            int   d_cnt[MAXB];          // edges per graph
__device__ __align__(16) float d_Q [128];         // sum of a^2 over all edges
__device__ __align__(16) float d_s1[128], d_t2[128];
__device__ __align__(16) float d_S1[128], d_Q1[128], d_S2[128], d_Q2[128];
__device__ __align__(16) float d_a1[MAXB * 128], d_a2[MAXB * 128];
__device__            int   d_f_e64, d_f_b64;     // 1 if int64-encoded, else int32

// ---------------- helpers ----------------
__device__ __forceinline__ void red4(float* p, float4 v) {
    asm volatile("red.global.add.v4.f32 [%0], {%1,%2,%3,%4};"
                 :: "l"(p), "f"(v.x), "f"(v.y), "f"(v.z), "f"(v.w) : "memory");
}

#define DUP2(d, f)        asm("mov.b64 %0, {%1, %1};" : "=l"(d) : "f"(f))
#define UNPK2(lo, hi, v)  asm("mov.b64 {%0, %1}, %2;" : "=f"(lo), "=f"(hi) : "l"(v))
#define PK2(d, lo, hi)    asm("mov.b64 %0, {%1, %2};" : "=l"(d) : "f"(lo), "f"(hi))
#define FFMA2(acc, a, b)  asm("fma.rn.f32x2 %0, %1, %2, %0;" : "+l"(acc) : "l"(a), "l"(b))

__device__ __forceinline__ long long ldix(const void* p, long long i, int is64) {
    return is64 ? ((const long long*)p)[i] : (long long)((const int*)p)[i];
}

__device__ __forceinline__ float leaky(float z) { return z >= 0.f ? z : SLOPE * z; }

// ---------------- K0: zero scratch + detect index width ----------------
__global__ void k_init(const void* eidx, const void* bat,
                       long long e2w, long long nw) {
    int idx = blockIdx.x * blockDim.x + threadIdx.x;
    int stride = gridDim.x * blockDim.x;
    for (int i = idx; i < MAXB * 128; i += stride) d_A[i] = 0.f;
    for (int i = idx; i < MAXB * 64;  i += stride) d_gx[i] = 0.f;
    for (int i = idx; i < MAXB;       i += stride) d_cnt[i] = 0;
    for (int i = idx; i < 128;        i += stride) {
        d_Q[i] = 0.f; d_S1[i] = 0.f; d_Q1[i] = 0.f; d_S2[i] = 0.f; d_Q2[i] = 0.f;
    }
    // detection: warp 0 of block 0 samples odd 32-bit words; int64 => high halves all 0
    if (blockIdx.x == 0 && threadIdx.x < 32) {
        const unsigned* we = (const unsigned*)eidx;
        const unsigned* wb = (const unsigned*)bat;
        int lane = threadIdx.x;
        int nz_e = 0, nz_b = 0;
        long long se = e2w / 64; if (se < 2) se = 2;
        long long sb = nw  / 64; if (sb < 2) sb = 2;
        for (int s = 0; s < 2; ++s) {
            long long k = lane * 2 + s;
            long long pe = (k * se) | 1; if (pe >= e2w) pe = 1;
            long long pb = (k * sb) | 1; if (pb >= nw)  pb = 1;
            if (we[pe] != 0u) nz_e++;
            if (wb[pb] != 0u) nz_b++;
        }
        for (int o = 16; o > 0; o >>= 1) {
            nz_e += __shfl_xor_sync(0xffffffffu, nz_e, o);
            nz_b += __shfl_xor_sync(0xffffffffu, nz_b, o);
        }
        if (lane == 0) {
            d_f_e64 = (nz_e < 8) ? 1 : 0;
            d_f_b64 = (nz_b < 8) ? 1 : 0;
        }
    }
}

// ---------------- K1: fused gather + GEMM1 + leaky + scatter(A,Q,cnt) ----------------
// Block: 256 threads, 128 edges. Thread (tx=tid&15, ty=tid>>4):
// 8 edges (ty*8..+7), 8 cols ({4tx..4tx+3} and {64+4tx..+3}).
__global__ __launch_bounds__(256, 2)
void k_edge(const float* __restrict__ x, const void* __restrict__ eidx,
            const float* __restrict__ ea, const void* __restrict__ bat,
            const float* __restrict__ W1a, const float* __restrict__ b1a,
            long long E) {
    __shared__ float As[32 * 128];
    __shared__ float Ws[32 * 128];
    __shared__ int   srow[128];
    __shared__ int   sg[128];

    const int tid = threadIdx.x;
    const long long e0 = (long long)blockIdx.x * 128;
    const int e64 = d_f_e64, b64 = d_f_b64;

    if (tid < 128) {
        long long e = e0 + tid;
        int r = 0, g = 0;
        if (e < E) {
            r = (int)ldix(eidx, e, e64);
            long long cc = ldix(eidx, E + e, e64);
            g = (int)ldix(bat, cc, b64);
        }
        srow[tid] = r;
        sg[tid]   = g;
    }

    const int tx = tid & 15, ty = tid >> 4;
    const int c0 = 4 * tx, c1 = 64 + 4 * tx;

    unsigned long long acc[8][4];
    {
        float4 bb0 = *(const float4*)(b1a + c0);
        float4 bb1 = *(const float4*)(b1a + c1);
        unsigned long long p0, p1, p2, p3;
        PK2(p0, bb0.x, bb0.y); PK2(p1, bb0.z, bb0.w);
        PK2(p2, bb1.x, bb1.y); PK2(p3, bb1.z, bb1.w);
        #pragma unroll
        for (int e = 0; e < 8; ++e) {
            acc[e][0] = p0; acc[e][1] = p1; acc[e][2] = p2; acc[e][3] = p3;
        }
    }
    __syncthreads();   // srow/sg visible

    const int el = tid & 127;
    const int f4base = (tid >> 7) * 4;   // 0 or 4

    for (int c = 0; c < 4; ++c) {
        // --- stage W chunk [32k x 128] (contiguous copy) ---
        const float4* wsrc = (const float4*)(W1a + c * 32 * 128);
        float4* wdst = (float4*)Ws;
        #pragma unroll
        for (int i = 0; i < 4; ++i) wdst[tid + i * 256] = wsrc[tid + i * 256];

        // --- stage A chunk [32k x 128 edges], k-major ---
        #pragma unroll
        for (int i = 0; i < 4; ++i) {
            int fq = f4base + i;                 // float4 index 0..7 within chunk
            float4 v;
            if (c < 2) {
                const float4* src = (const float4*)(x + (long long)srow[el] * 64 + c * 32);
                v = src[fq];
            } else {
                long long e = e0 + el;
                if (e < E) {
                    const float4* src = (const float4*)(ea + e * 64 + (c - 2) * 32);
                    v = src[fq];
                } else v = make_float4(0.f, 0.f, 0.f, 0.f);
            }
            int kk = fq * 4;
            As[(kk + 0) * 128 + el] = v.x;
            As[(kk + 1) * 128 + el] = v.y;
            As[(kk + 2) * 128 + el] = v.z;
            As[(kk + 3) * 128 + el] = v.w;
        }
        __syncthreads();

        // --- mainloop: 32 k-steps, FFMA2 ---
        #pragma unroll 8
        for (int kk = 0; kk < 32; ++kk) {
            const float* ar = &As[kk * 128 + ty * 8];
            float2 a01 = *(const float2*)(ar + 0);
            float2 a23 = *(const float2*)(ar + 2);
            float2 a45 = *(const float2*)(ar + 4);
            float2 a67 = *(const float2*)(ar + 6);
            const float* wr = &Ws[kk * 128];
            unsigned long long w0 = *(const unsigned long long*)(wr + c0);
            unsigned long long w1 = *(const unsigned long long*)(wr + c0 + 2);
            unsigned long long w2 = *(const unsigned long long*)(wr + c1);
            unsigned long long w3 = *(const unsigned long long*)(wr + c1 + 2);
            unsigned long long ad[8];
            DUP2(ad[0], a01.x); DUP2(ad[1], a01.y);
            DUP2(ad[2], a23.x); DUP2(ad[3], a23.y);
            DUP2(ad[4], a45.x); DUP2(ad[5], a45.y);
            DUP2(ad[6], a67.x); DUP2(ad[7], a67.y);
            #pragma unroll
            for (int e = 0; e < 8; ++e) {
                FFMA2(acc[e][0], ad[e], w0);
                FFMA2(acc[e][1], ad[e], w1);
                FFMA2(acc[e][2], ad[e], w2);
                FFMA2(acc[e][3], ad[e], w3);
            }
        }
        __syncthreads();
    }

    // --- epilogue: leaky, scatter to graph bins, Q stats, edge counts ---
    float qc[8];
    #pragma unroll
    for (int j = 0; j < 8; ++j) qc[j] = 0.f;

    #pragma unroll
    for (int e = 0; e < 8; ++e) {
        long long eg = e0 + ty * 8 + e;
        bool valid = eg < E;
        int g = sg[ty * 8 + e];
        float z[8];
        UNPK2(z[0], z[1], acc[e][0]);
        UNPK2(z[2], z[3], acc[e][1]);
        UNPK2(z[4], z[5], acc[e][2]);
        UNPK2(z[6], z[7], acc[e][3]);
        #pragma unroll
        for (int j = 0; j < 8; ++j) {
            float a = leaky(z[j]);
            z[j] = a;
            if (valid) qc[j] += a * a;
        }
        if (valid) {
            float* base = d_A + (long long)g * 128;
            red4(base + c0, make_float4(z[0], z[1], z[2], z[3]));
            red4(base + c1, make_float4(z[4], z[5], z[6], z[7]));
            if (tx == 0) atomicAdd(&d_cnt[g], 1);
        }
    }

    // fold Q across the two ty's sharing a warp, then one red4 per lane<16
    #pragma unroll
    for (int j = 0; j < 8; ++j) qc[j] += __shfl_xor_sync(0xffffffffu, qc[j], 16);
    if ((tid & 16) == 0) {
        red4(d_Q + c0, make_float4(qc[0], qc[1], qc[2], qc[3]));
        red4(d_Q + c1, make_float4(qc[4], qc[5], qc[6], qc[7]));
    }
}

// ---------------- K2: gx[b] += x[node] ----------------
__global__ void k_gx(const float* __restrict__ x, const void* __restrict__ bat,
                     long long N) {
    long long idx = (long long)blockIdx.x * blockDim.x + threadIdx.x;
    if (idx >= N * 16) return;
    long long node = idx >> 4;
    int q = (int)(idx & 15);
    int g = (int)ldix(bat, node, d_f_b64);
    float4 v = ((const float4*)x)[node * 16 + q];
    red4(d_gx + (long long)g * 64 + q * 4, v);
}

// ---------------- K2.5: BN1a fold + t2eff = t1@W2a + b2a ----------------
__global__ void k_prep(const float* __restrict__ W2a, const float* __restrict__ b2a,
                       const float* __restrict__ g1a, const float* __restrict__ be1a,
                       float Ef, int B) {
    __shared__ float st1[128];
    int j = threadIdx.x;
    float S = 0.f;
    for (int b = 0; b < B; ++b) S += d_A[b * 128 + j];
    float m = S / Ef;
    float v = d_Q[j] / Ef - m * m;
    float s = g1a[j] * rsqrtf(v + EPS);
    float t = be1a[j] - m * s;
    d_s1[j] = s;
    st1[j] = t;
    __syncthreads();
    float a = b2a[j];
    #pragma unroll 8
    for (int k = 0; k < 128; ++k) a += st1[k] * W2a[k * 128 + j];
    d_t2[j] = a;
}

// ---------------- K3: ga + first graph layer + stats ----------------
__global__ void k_g1(const float* __restrict__ W2a,
                     const float* __restrict__ W1b, const float* __restrict__ b1b) {
    __shared__ float sAs[128], sga[128], sgx[64];
    int b = blockIdx.x, j = threadIdx.x;
    sAs[j] = d_A[b * 128 + j] * d_s1[j];
    if (j < 64) sgx[j] = d_gx[b * 64 + j];
    __syncthreads();
    float cf = (float)d_cnt[b];
    float ga = d_t2[j] * cf;
    #pragma unroll 8
    for (int k = 0; k < 128; ++k) ga += sAs[k] * W2a[k * 128 + j];
    sga[j] = ga;
    __syncthreads();
    float z = b1b[j];
    #pragma unroll 8
    for (int i = 0; i < 64; ++i)  z += sgx[i] * W1b[i * 128 + j];
    #pragma unroll 8
    for (int i = 0; i < 128; ++i) z += sga[i] * W1b[(64 + i) * 128 + j];
    float a = leaky(z);
    d_a1[b * 128 + j] = a;
    atomicAdd(&d_S1[j], a);
    atomicAdd(&d_Q1[j], a * a);
}

// ---------------- K4: BN1b + second graph layer + stats ----------------
__global__ void k_g2(const float* __restrict__ W2b, const float* __restrict__ b2b,
                     const float* __restrict__ g1b, const float* __restrict__ be1b,
                     float Bf) {
    __shared__ float sh[128];
    int b = blockIdx.x, j = threadIdx.x;
    float m = d_S1[j] / Bf;
    float v = d_Q1[j] / Bf - m * m;
    float s = g1b[j] * rsqrtf(v + EPS);
    float t = be1b[j] - m * s;
    sh[j] = d_a1[b * 128 + j] * s + t;
    __syncthreads();
    float z = b2b[j];
    #pragma unroll 8
    for (int k = 0; k < 128; ++k) z += sh[k] * W2b[k * 128 + j];
    float a = leaky(z);
    d_a2[b * 128 + j] = a;
    atomicAdd(&d_S2[j], a);
    atomicAdd(&d_Q2[j], a * a);
}

// ---------------- K5: BN2b + output layer ----------------
__global__ void k_g3(const float* __restrict__ W3b, const float* __restrict__ b3b,
                     const float* __restrict__ g2b, const float* __restrict__ be2b,
                     float Bf, float* __restrict__ out) {
    __shared__ float sh[128];
    int b = blockIdx.x, j = threadIdx.x;
    float m = d_S2[j] / Bf;
    float v = d_Q2[j] / Bf - m * m;
    float s = g2b[j] * rsqrtf(v + EPS);
    float t = be2b[j] - m * s;
    sh[j] = d_a2[b * 128 + j] * s + t;
    __syncthreads();
    float z = b3b[j];
    #pragma unroll 8
    for (int k = 0; k < 128; ++k) z += sh[k] * W3b[k * 128 + j];
    out[b * 128 + j] = z;
}

// ---------------- launch ----------------
extern "C" void kernel_launch(void* const* d_in, const int* in_sizes, int n_in,
                              void* d_out, int out_size) {
    const float* x    = (const float*)d_in[0];
    const void*  ei   = d_in[1];
    const float* ea   = (const float*)d_in[2];
    const void*  bat  = d_in[4];
    const float* W1a  = (const float*)d_in[5];
    const float* b1a  = (const float*)d_in[6];
    const float* g1a  = (const float*)d_in[7];
    const float* be1a = (const float*)d_in[8];
    const float* W2a  = (const float*)d_in[9];
    const float* b2a  = (const float*)d_in[10];
    const float* W1b  = (const float*)d_in[11];
    const float* b1b  = (const float*)d_in[12];
    const float* g1b  = (const float*)d_in[13];
    const float* be1b = (const float*)d_in[14];
    const float* W2b  = (const float*)d_in[15];
    const float* b2b  = (const float*)d_in[16];
    const float* g2b  = (const float*)d_in[17];
    const float* be2b = (const float*)d_in[18];
    const float* W3b  = (const float*)d_in[19];
    const float* b3b  = (const float*)d_in[20];

    long long N = (long long)in_sizes[0] / 64;
    long long E = (long long)in_sizes[2] / 64;
    int B = in_sizes[3];
    if (B > MAXB) B = MAXB;

    k_init<<<256, 256>>>(ei, bat, 2 * E, N);

    int gridE = (int)((E + 127) / 128);
    k_edge<<<gridE, 256>>>(x, ei, ea, bat, W1a, b1a, E);

    int gridN = (int)((N * 16 + 255) / 256);
    k_gx<<<gridN, 256>>>(x, bat, N);

    k_prep<<<1, 128>>>(W2a, b2a, g1a, be1a, (float)E, B);
    k_g1<<<B, 128>>>(W2a, W1b, b1b);
    k_g2<<<B, 128>>>(W2b, b2b, g1b, be1b, (float)B);
    k_g3<<<B, 128>>>(W3b, b3b, g2b, be2b, (float)B, (float*)d_out);
}

// round 9
// speedup vs baseline: 1.3631x; 1.3631x over previous
#include <cuda_runtime.h>
#include <cuda_bf16.h>
#include <cstdint>

#define MAXB  1024
#define EPS   1e-5f
#define SLOPE 0.01f

// ---------------- static device scratch (no allocations allowed) ----------------
__device__ __align__(16) float d_A [MAXB * 128];  // per-graph sum of a_e
__device__ __align__(16) float d_gx[MAXB * 64];   // per-graph sum of x
__device__            int   d_cnt[MAXB];          // edges per graph
__device__ __align__(16) float d_Q [128];         // sum of a^2 over all edges
__device__ __align__(16) float d_s1[128], d_t1[128], d_t2[128];
__device__ __align__(16) float d_S1[128], d_Q1[128], d_S2[128], d_Q2[128];
__device__ __align__(16) float d_a1[MAXB * 128], d_a2[MAXB * 128];
__device__ __align__(16) unsigned short d_Wt[34816]; // W^T bf16: hi[128][136], lo[128][136]
__device__            int   d_f_e64, d_f_b64;     // 1 if int64-encoded, else int32

// ---------------- smem layout of k_edge (dynamic) ----------------
#define S_SROW 0
#define S_SG   512
#define S_CNT  1024                 // 1024 ints
#define S_W    5120                 // Whi [128][272B]
#define S_WL   (S_W + 34816)        // Wlo
#define S_A    (S_W + 69632)        // Ahi [128][272B]
#define S_AL   (S_A + 34816)        // Alo
#define SMEM_TOT (S_A + 69632)      // 144384

// ---------------- helpers ----------------
__device__ __forceinline__ void red4(float* p, float4 v) {
    asm volatile("red.global.add.v4.f32 [%0], {%1,%2,%3,%4};"
                 :: "l"(p), "f"(v.x), "f"(v.y), "f"(v.z), "f"(v.w) : "memory");
}
__device__ __forceinline__ long long ldix(const void* p, long long i, int is64) {
    return is64 ? ((const long long*)p)[i] : (long long)((const int*)p)[i];
}
__device__ __forceinline__ float leaky(float z) { return z >= 0.f ? z : SLOPE * z; }
__device__ __forceinline__ uint32_t smem_u32(const void* p) {
    uint32_t a;
    asm("{ .reg .u64 t; cvta.to.shared.u64 t, %1; cvt.u32.u64 %0, t; }" : "=r"(a) : "l"(p));
    return a;
}
#define LDSM4(r, a) \
    asm volatile("ldmatrix.sync.aligned.m8n8.x4.shared.b16 {%0,%1,%2,%3}, [%4];" \
        : "=r"((r)[0]), "=r"((r)[1]), "=r"((r)[2]), "=r"((r)[3]) : "r"(a))
#define MMA16816(c, a, b0, b1) \
    asm volatile("mma.sync.aligned.m16n8k16.row.col.f32.bf16.bf16.f32 " \
        "{%0,%1,%2,%3}, {%4,%5,%6,%7}, {%8,%9}, {%0,%1,%2,%3};" \
        : "+f"((c)[0]), "+f"((c)[1]), "+f"((c)[2]), "+f"((c)[3]) \
        : "r"((a)[0]), "r"((a)[1]), "r"((a)[2]), "r"((a)[3]), "r"(b0), "r"(b1))

// ---------------- K0: zero scratch + detect index width ----------------
__global__ void k_init(const void* eidx, const void* bat,
                       long long e2w, long long nw) {
    int idx = blockIdx.x * blockDim.x + threadIdx.x;
    int stride = gridDim.x * blockDim.x;
    for (int i = idx; i < MAXB * 128; i += stride) d_A[i] = 0.f;
    for (int i = idx; i < MAXB * 64;  i += stride) d_gx[i] = 0.f;
    for (int i = idx; i < MAXB;       i += stride) d_cnt[i] = 0;
    for (int i = idx; i < 128;        i += stride) {
        d_Q[i] = 0.f; d_S1[i] = 0.f; d_Q1[i] = 0.f; d_S2[i] = 0.f; d_Q2[i] = 0.f;
    }
    if (blockIdx.x == 0 && threadIdx.x < 32) {
        const unsigned* we = (const unsigned*)eidx;
        const unsigned* wb = (const unsigned*)bat;
        int lane = threadIdx.x;
        int nz_e = 0, nz_b = 0;
        long long se = e2w / 64; if (se < 2) se = 2;
        long long sb = nw  / 64; if (sb < 2) sb = 2;
        for (int s = 0; s < 2; ++s) {
            long long k = lane * 2 + s;
            long long pe = (k * se) | 1; if (pe >= e2w) pe = 1;
            long long pb = (k * sb) | 1; if (pb >= nw)  pb = 1;
            if (we[pe] != 0u) nz_e++;
            if (wb[pb] != 0u) nz_b++;
        }
        for (int o = 16; o > 0; o >>= 1) {
            nz_e += __shfl_xor_sync(0xffffffffu, nz_e, o);
            nz_b += __shfl_xor_sync(0xffffffffu, nz_b, o);
        }
        if (lane == 0) {
            d_f_e64 = (nz_e < 8) ? 1 : 0;
            d_f_b64 = (nz_b < 8) ? 1 : 0;
        }
    }
}

// ---------------- K0.5: W1a -> W^T bf16 hi/lo, padded rows (136 elems) ----------------
__global__ void k_wprep(const float* __restrict__ W1a) {
    int tid = blockIdx.x * blockDim.x + threadIdx.x;
    if (tid >= 16384) return;
    int k = tid >> 7, n = tid & 127;
    float w = W1a[k * 128 + n];
    __nv_bfloat16 h = __float2bfloat16(w);
    __nv_bfloat16 l = __float2bfloat16(w - __bfloat162float(h));
    d_Wt[n * 136 + k]          = *(unsigned short*)&h;
    d_Wt[17408 + n * 136 + k]  = *(unsigned short*)&l;
}

// ---------------- K1: gx[b] += x[node]  (also warms x into L2) ----------------
__global__ void k_gx(const float* __restrict__ x, const void* __restrict__ bat,
                     long long N) {
    long long idx = (long long)blockIdx.x * blockDim.x + threadIdx.x;
    if (idx >= N * 16) return;
    long long node = idx >> 4;
    int q = (int)(idx & 15);
    int g = (int)ldix(bat, node, d_f_b64);
    float4 v = ((const float4*)x)[node * 16 + q];
    red4(d_gx + (long long)g * 64 + q * 4, v);
}

// ---------------- K2: persistent mma.sync edge kernel ----------------
// Tile = 128 edges x 128 cols. 8 warps: warp grid 4m x 2n, warp tile 32e x 64j.
// D = (Ahi+Alo) @ (Whi+Wlo)^T via 3 bf16 products, fp32 accum in regs.
__global__ __launch_bounds__(256, 1)
void k_edge(const float* __restrict__ x, const void* __restrict__ eidx,
            const float* __restrict__ ea, const void* __restrict__ bat,
            const float* __restrict__ b1a, long long E, int ntiles) {
    extern __shared__ char smem[];
    const uint32_t sb = smem_u32(smem);
    const int tid = threadIdx.x, wid = tid >> 5, lane = tid & 31;
    const int e64 = d_f_e64, b64 = d_f_b64;
    const int wm = wid & 3, wn = wid >> 2;
    const int rowb = wm * 32, colb = wn * 64;

    // one-time: W tiles (69.6KB) + smem cnt zero
    {
        const uint4* wsrc = (const uint4*)d_Wt;
        uint4* wdst = (uint4*)(smem + S_W);
        for (int i = tid; i < 4352; i += 256) wdst[i] = wsrc[i];
    }
    for (int i = tid; i < MAXB; i += 256) *(int*)(smem + S_CNT + i * 4) = 0;

    // bias for this lane's columns (fixed across tiles)
    float bb0[8], bb1[8];
    #pragma unroll
    for (int ni = 0; ni < 8; ++ni) {
        int colp = colb + ni * 8 + 2 * (lane & 3);
        bb0[ni] = b1a[colp];
        bb1[ni] = b1a[colp + 1];
    }
    float q0[8], q1[8];
    #pragma unroll
    for (int ni = 0; ni < 8; ++ni) { q0[ni] = 0.f; q1[ni] = 0.f; }

    // ldmatrix lane-address components
    const int arow = lane & 15;
    const int akof = (lane >> 4) * 16;                       // bytes
    const int brow = (lane & 7) + ((lane & 16) >> 1);
    const int bkof = ((lane >> 3) & 1) * 16;                 // bytes
    const int quad = 4 * ((lane & 3) >> 1);

    for (int t = blockIdx.x; t < ntiles; t += gridDim.x) {
        const long long e0 = (long long)t * 128;
        __syncthreads();                        // prior LDSM/epilogue reads done
        if (tid < 128) {
            long long e = e0 + tid;
            int r = 0, g = 0;
            if (e < E) {
                r = (int)ldix(eidx, e, e64);
                long long c2 = ldix(eidx, E + e, e64);
                g = (int)ldix(bat, c2, b64);
            }
            *(int*)(smem + S_SROW + tid * 4) = r;
            *(int*)(smem + S_SG   + tid * 4) = g;
        }
        __syncthreads();
        if (tid < 128 && (e0 + tid) < E)
            atomicAdd((int*)(smem + S_CNT + (*(int*)(smem + S_SG + tid * 4)) * 4), 1);

        // ---- stage A: gather + fp32 -> bf16 hi/lo, 272B-padded rows ----
        {
            int el = tid >> 1, cc = tid & 1;
            long long eg = e0 + el;
            const float4* src;
            bool ok = true;
            if (cc == 0) {
                int r = *(const int*)(smem + S_SROW + el * 4);
                src = (const float4*)(x + (size_t)r * 64);
            } else {
                src = (const float4*)(ea + eg * 64);
                ok = eg < E;
            }
            char* ah = smem + S_A  + el * 272 + cc * 128;
            char* al = smem + S_AL + el * 272 + cc * 128;
            #pragma unroll
            for (int i = 0; i < 16; ++i) {
                float4 v = ok ? src[i] : make_float4(0.f, 0.f, 0.f, 0.f);
                __nv_bfloat162 h01 = __floats2bfloat162_rn(v.x, v.y);
                __nv_bfloat162 h23 = __floats2bfloat162_rn(v.z, v.w);
                float lx = v.x - __bfloat162float(h01.x);
                float ly = v.y - __bfloat162float(h01.y);
                float lz = v.z - __bfloat162float(h23.x);
                float lw = v.w - __bfloat162float(h23.y);
                __nv_bfloat162 l01 = __floats2bfloat162_rn(lx, ly);
                __nv_bfloat162 l23 = __floats2bfloat162_rn(lz, lw);
                *(uint2*)(ah + i * 8) = make_uint2(*(uint32_t*)&h01, *(uint32_t*)&h23);
                *(uint2*)(al + i * 8) = make_uint2(*(uint32_t*)&l01, *(uint32_t*)&l23);
            }
        }
        __syncthreads();

        // ---- MMA mainloop ----
        float c[2][8][4];
        #pragma unroll
        for (int mi = 0; mi < 2; ++mi)
            #pragma unroll
            for (int ni = 0; ni < 8; ++ni)
                #pragma unroll
                for (int j = 0; j < 4; ++j) c[mi][ni][j] = 0.f;

        #pragma unroll
        for (int kk = 0; kk < 8; ++kk) {
            uint32_t ah[2][4], al_[2][4];
            #pragma unroll
            for (int mi = 0; mi < 2; ++mi) {
                uint32_t aaddr = sb + S_A + (uint32_t)(rowb + mi * 16 + arow) * 272
                                 + kk * 32 + akof;
                LDSM4(ah[mi], aaddr);
                LDSM4(al_[mi], aaddr + 34816u);
            }
            #pragma unroll
            for (int np = 0; np < 4; ++np) {
                uint32_t baddr = sb + S_W + (uint32_t)(colb + np * 16 + brow) * 272
                                 + kk * 32 + bkof;
                uint32_t bh[4];
                LDSM4(bh, baddr);
                #pragma unroll
                for (int mi = 0; mi < 2; ++mi) {
                    MMA16816(c[mi][np * 2 + 0], ah[mi],  bh[0], bh[1]);
                    MMA16816(c[mi][np * 2 + 1], ah[mi],  bh[2], bh[3]);
                    MMA16816(c[mi][np * 2 + 0], al_[mi], bh[0], bh[1]);
                    MMA16816(c[mi][np * 2 + 1], al_[mi], bh[2], bh[3]);
                }
                uint32_t bl[4];
                LDSM4(bl, baddr + 34816u);
                #pragma unroll
                for (int mi = 0; mi < 2; ++mi) {
                    MMA16816(c[mi][np * 2 + 0], ah[mi], bl[0], bl[1]);
                    MMA16816(c[mi][np * 2 + 1], ah[mi], bl[2], bl[3]);
                }
            }
        }

        // ---- epilogue: bias + leaky + Q accum + pairwise shuffle + red4 scatter ----
        #pragma unroll
        for (int mi = 0; mi < 2; ++mi) {
            int rA = rowb + mi * 16 + (lane >> 2);
            int rB = rA + 8;
            bool vA = (e0 + rA) < E, vB = (e0 + rB) < E;
            int gA = *(const int*)(smem + S_SG + rA * 4);
            int gB = *(const int*)(smem + S_SG + rB * 4);
            #pragma unroll
            for (int ni = 0; ni < 8; ++ni) {
                float a0 = leaky(c[mi][ni][0] + bb0[ni]);
                float a1 = leaky(c[mi][ni][1] + bb1[ni]);
                float a2 = leaky(c[mi][ni][2] + bb0[ni]);
                float a3 = leaky(c[mi][ni][3] + bb1[ni]);
                if (vA) { q0[ni] += a0 * a0; q1[ni] += a1 * a1; }
                if (vB) { q0[ni] += a2 * a2; q1[ni] += a3 * a3; }
                float x0 = __shfl_xor_sync(0xffffffffu, a0, 1);
                float x1 = __shfl_xor_sync(0xffffffffu, a1, 1);
                float x2 = __shfl_xor_sync(0xffffffffu, a2, 1);
                float x3 = __shfl_xor_sync(0xffffffffu, a3, 1);
                int col = colb + ni * 8 + quad;
                if ((lane & 1) == 0) {
                    if (vA) red4(d_A + (size_t)gA * 128 + col, make_float4(a0, a1, x0, x1));
                } else {
                    if (vB) red4(d_A + (size_t)gB * 128 + col, make_float4(x2, x3, a2, a3));
                }
            }
        }
    }

    // ---- flush Q (cross-lane reduce within col groups, then global atomics) ----
    #pragma unroll
    for (int ni = 0; ni < 8; ++ni) {
        #pragma unroll
        for (int o = 4; o < 32; o <<= 1) {
            q0[ni] += __shfl_xor_sync(0xffffffffu, q0[ni], o);
            q1[ni] += __shfl_xor_sync(0xffffffffu, q1[ni], o);
        }
    }
    if (lane < 4) {
        #pragma unroll
        for (int ni = 0; ni < 8; ++ni) {
            int colp = colb + ni * 8 + 2 * lane;
            atomicAdd(&d_Q[colp],     q0[ni]);
            atomicAdd(&d_Q[colp + 1], q1[ni]);
        }
    }
    // ---- flush edge counts ----
    __syncthreads();
    for (int i = tid; i < MAXB; i += 256) {
        int v = *(const int*)(smem + S_CNT + i * 4);
        if (v) atomicAdd(&d_cnt[i], v);
    }
}

// ---------------- K3: BN1a stats (parallel over 128 cols) ----------------
__global__ void k_stats(const float* __restrict__ g1a, const float* __restrict__ be1a,
                        float Ef, int B) {
    __shared__ float red_s[128];
    int j = blockIdx.x;
    float s = 0.f;
    for (int b = threadIdx.x; b < B; b += 128) s += d_A[b * 128 + j];
    red_s[threadIdx.x] = s;
    __syncthreads();
    for (int o = 64; o; o >>= 1) {
        if (threadIdx.x < o) red_s[threadIdx.x] += red_s[threadIdx.x + o];
        __syncthreads();
    }
    if (threadIdx.x == 0) {
        float m = red_s[0] / Ef;
        float v = d_Q[j] / Ef - m * m;
        float sc = g1a[j] * rsqrtf(v + EPS);
        d_s1[j] = sc;
        d_t1[j] = be1a[j] - m * sc;
    }
}

// ---------------- K3.5: t2 = t1 @ W2a + b2a ----------------
__global__ void k_prep2(const float* __restrict__ W2a, const float* __restrict__ b2a) {
    __shared__ float st[128];
    int j = threadIdx.x;
    st[j] = d_t1[j];
    __syncthreads();
    float a = b2a[j];
    #pragma unroll 8
    for (int k = 0; k < 128; ++k) a += st[k] * W2a[k * 128 + j];
    d_t2[j] = a;
}

// ---------------- K4: ga + first graph layer + stats ----------------
__global__ void k_g1(const float* __restrict__ W2a,
                     const float* __restrict__ W1b, const float* __restrict__ b1b) {
    __shared__ float sAs[128], sga[128], sgx[64];
    int b = blockIdx.x, j = threadIdx.x;
    sAs[j] = d_A[b * 128 + j] * d_s1[j];
    if (j < 64) sgx[j] = d_gx[b * 64 + j];
    __syncthreads();
    float cf = (float)d_cnt[b];
    float ga = d_t2[j] * cf;
    #pragma unroll 8
    for (int k = 0; k < 128; ++k) ga += sAs[k] * W2a[k * 128 + j];
    sga[j] = ga;
    __syncthreads();
    float z = b1b[j];
    #pragma unroll 8
    for (int i = 0; i < 64; ++i)  z += sgx[i] * W1b[i * 128 + j];
    #pragma unroll 8
    for (int i = 0; i < 128; ++i) z += sga[i] * W1b[(64 + i) * 128 + j];
    float a = leaky(z);
    d_a1[b * 128 + j] = a;
    atomicAdd(&d_S1[j], a);
    atomicAdd(&d_Q1[j], a * a);
}

// ---------------- K5: BN1b + second graph layer + stats ----------------
__global__ void k_g2(const float* __restrict__ W2b, const float* __restrict__ b2b,
                     const float* __restrict__ g1b, const float* __restrict__ be1b,
                     float Bf) {
    __shared__ float sh[128];
    int b = blockIdx.x, j = threadIdx.x;
    float m = d_S1[j] / Bf;
    float v = d_Q1[j] / Bf - m * m;
    float s = g1b[j] * rsqrtf(v + EPS);
    float t = be1b[j] - m * s;
    sh[j] = d_a1[b * 128 + j] * s + t;
    __syncthreads();
    float z = b2b[j];
    #pragma unroll 8
    for (int k = 0; k < 128; ++k) z += sh[k] * W2b[k * 128 + j];
    float a = leaky(z);
    d_a2[b * 128 + j] = a;
    atomicAdd(&d_S2[j], a);
    atomicAdd(&d_Q2[j], a * a);
}

// ---------------- K6: BN2b + output layer ----------------
__global__ void k_g3(const float* __restrict__ W3b, const float* __restrict__ b3b,
                     const float* __restrict__ g2b, const float* __restrict__ be2b,
                     float Bf, float* __restrict__ out) {
    __shared__ float sh[128];
    int b = blockIdx.x, j = threadIdx.x;
    float m = d_S2[j] / Bf;
    float v = d_Q2[j] / Bf - m * m;
    float s = g2b[j] * rsqrtf(v + EPS);
    float t = be2b[j] - m * s;
    sh[j] = d_a2[b * 128 + j] * s + t;
    __syncthreads();
    float z = b3b[j];
    #pragma unroll 8
    for (int k = 0; k < 128; ++k) z += sh[k] * W3b[k * 128 + j];
    out[b * 128 + j] = z;
}

// ---------------- launch ----------------
extern "C" void kernel_launch(void* const* d_in, const int* in_sizes, int n_in,
                              void* d_out, int out_size) {
    const float* x    = (const float*)d_in[0];
    const void*  ei   = d_in[1];
    const float* ea   = (const float*)d_in[2];
    const void*  bat  = d_in[4];
    const float* W1a  = (const float*)d_in[5];
    const float* b1a  = (const float*)d_in[6];
    const float* g1a  = (const float*)d_in[7];
    const float* be1a = (const float*)d_in[8];
    const float* W2a  = (const float*)d_in[9];
    const float* b2a  = (const float*)d_in[10];
    const float* W1b  = (const float*)d_in[11];
    const float* b1b  = (const float*)d_in[12];
    const float* g1b  = (const float*)d_in[13];
    const float* be1b = (const float*)d_in[14];
    const float* W2b  = (const float*)d_in[15];
    const float* b2b  = (const float*)d_in[16];
    const float* g2b  = (const float*)d_in[17];
    const float* be2b = (const float*)d_in[18];
    const float* W3b  = (const float*)d_in[19];
    const float* b3b  = (const float*)d_in[20];

    long long N = (long long)in_sizes[0] / 64;
    long long E = (long long)in_sizes[2] / 64;
    int B = in_sizes[3];
    if (B > MAXB) B = MAXB;

    static int smem_set = 0;
    if (!smem_set) {
        cudaFuncSetAttribute(k_edge, cudaFuncAttributeMaxDynamicSharedMemorySize, SMEM_TOT);
        smem_set = 1;
    }

    k_init<<<256, 256>>>(ei, bat, 2 * E, N);
    k_wprep<<<64, 256>>>(W1a);

    int gridN = (int)((N * 16 + 255) / 256);
    k_gx<<<gridN, 256>>>(x, bat, N);           // also warms x into L2 for gathers

    int ntiles = (int)((E + 127) / 128);
    int grid = ntiles < 148 ? ntiles : 148;
    k_edge<<<grid, 256, SMEM_TOT>>>(x, ei, ea, bat, b1a, E, ntiles);

    k_stats<<<128, 128>>>(g1a, be1a, (float)E, B);
    k_prep2<<<1, 128>>>(W2a, b2a);
    k_g1<<<B, 128>>>(W2a, W1b, b1b);
    k_g2<<<B, 128>>>(W2b, b2b, g1b, be1b, (float)B);
    k_g3<<<B, 128>>>(W3b, b3b, g2b, be2b, (float)B, (float*)d_out);
}

// round 10
// speedup vs baseline: 1.5990x; 1.1731x over previous
#include <cuda_runtime.h>
#include <cuda_bf16.h>
#include <cstdint>

#define MAXB  1024
#define EPS   1e-5f
#define SLOPE 0.01f

// ---------------- static device scratch (no allocations allowed) ----------------
__device__ __align__(16) float d_A [MAXB * 128];  // per-graph sum of a_e
__device__ __align__(16) float d_gx[MAXB * 64];   // per-graph sum of x
__device__            int   d_cnt[MAXB];          // edges per graph
__device__ __align__(16) float d_Q [128];         // sum of a^2 over all edges
__device__ __align__(16) float d_s1[128], d_t1[128], d_t2[128];
__device__ __align__(16) float d_S1[128], d_Q1[128], d_S2[128], d_Q2[128];
__device__ __align__(16) float d_a1[MAXB * 128], d_a2[MAXB * 128];
__device__ __align__(16) unsigned short d_Wt[34816]; // W^T bf16: hi[128][136], lo[128][136]
__device__            int   d_f_e64, d_f_b64;     // 1 if int64-encoded, else int32

// ---------------- smem layout of k_edge (dynamic) ----------------
#define S_SG0   0            // sg parity buffers: 2 x 128 int
#define S_SG1   512
#define S_SR0   1024         // srow parity buffers
#define S_SR1   1536
#define S_CNT   2048         // 1024 ints
#define S_W     6144         // Whi [128][272B] then Wlo  (69632)
#define S_A     75776        // Ahi [128][272B] then Alo  (69632)
#define S_RAW   145408       // raw fp32 [128][132 floats] (67584)
#define SMEM_TOT 212992

// ---------------- helpers ----------------
__device__ __forceinline__ void red4(float* p, float4 v) {
    asm volatile("red.global.add.v4.f32 [%0], {%1,%2,%3,%4};"
                 :: "l"(p), "f"(v.x), "f"(v.y), "f"(v.z), "f"(v.w) : "memory");
}
__device__ __forceinline__ long long ldix(const void* p, long long i, int is64) {
    return is64 ? ((const long long*)p)[i] : (long long)((const int*)p)[i];
}
__device__ __forceinline__ float leaky(float z) { return z >= 0.f ? z : SLOPE * z; }
__device__ __forceinline__ uint32_t smem_u32(const void* p) {
    uint32_t a;
    asm("{ .reg .u64 t; cvta.to.shared.u64 t, %1; cvt.u32.u64 %0, t; }" : "=r"(a) : "l"(p));
    return a;
}
__device__ __forceinline__ void cpa16(uint32_t s, const void* g) {
    asm volatile("cp.async.cg.shared.global [%0], [%1], 16;" :: "r"(s), "l"(g) : "memory");
}
#define LDSM4(r, a) \
    asm volatile("ldmatrix.sync.aligned.m8n8.x4.shared.b16 {%0,%1,%2,%3}, [%4];" \
        : "=r"((r)[0]), "=r"((r)[1]), "=r"((r)[2]), "=r"((r)[3]) : "r"(a))
#define MMA16816(c, a, b0, b1) \
    asm volatile("mma.sync.aligned.m16n8k16.row.col.f32.bf16.bf16.f32 " \
        "{%0,%1,%2,%3}, {%4,%5,%6,%7}, {%8,%9}, {%0,%1,%2,%3};" \
        : "+f"((c)[0]), "+f"((c)[1]), "+f"((c)[2]), "+f"((c)[3]) \
        : "r"((a)[0]), "r"((a)[1]), "r"((a)[2]), "r"((a)[3]), "r"(b0), "r"(b1))

// ---------------- K0: zero scratch + detect index width ----------------
__global__ void k_init(const void* eidx, const void* bat,
                       long long e2w, long long nw) {
    int idx = blockIdx.x * blockDim.x + threadIdx.x;
    int stride = gridDim.x * blockDim.x;
    for (int i = idx; i < MAXB * 128; i += stride) d_A[i] = 0.f;
    for (int i = idx; i < MAXB * 64;  i += stride) d_gx[i] = 0.f;
    for (int i = idx; i < MAXB;       i += stride) d_cnt[i] = 0;
    for (int i = idx; i < 128;        i += stride) {
        d_Q[i] = 0.f; d_S1[i] = 0.f; d_Q1[i] = 0.f; d_S2[i] = 0.f; d_Q2[i] = 0.f;
    }
    if (blockIdx.x == 0 && threadIdx.x < 32) {
        const unsigned* we = (const unsigned*)eidx;
        const unsigned* wb = (const unsigned*)bat;
        int lane = threadIdx.x;
        int nz_e = 0, nz_b = 0;
        long long se = e2w / 64; if (se < 2) se = 2;
        long long sb = nw  / 64; if (sb < 2) sb = 2;
        for (int s = 0; s < 2; ++s) {
            long long k = lane * 2 + s;
            long long pe = (k * se) | 1; if (pe >= e2w) pe = 1;
            long long pb = (k * sb) | 1; if (pb >= nw)  pb = 1;
            if (we[pe] != 0u) nz_e++;
            if (wb[pb] != 0u) nz_b++;
        }
        for (int o = 16; o > 0; o >>= 1) {
            nz_e += __shfl_xor_sync(0xffffffffu, nz_e, o);
            nz_b += __shfl_xor_sync(0xffffffffu, nz_b, o);
        }
        if (lane == 0) {
            d_f_e64 = (nz_e < 8) ? 1 : 0;
            d_f_b64 = (nz_b < 8) ? 1 : 0;
        }
    }
}

// ---------------- K0.5: W1a -> W^T bf16 hi/lo, padded rows (136 elems) ----------------
__global__ void k_wprep(const float* __restrict__ W1a) {
    int tid = blockIdx.x * blockDim.x + threadIdx.x;
    if (tid >= 16384) return;
    int k = tid >> 7, n = tid & 127;
    float w = W1a[k * 128 + n];
    __nv_bfloat16 h = __float2bfloat16(w);
    __nv_bfloat16 l = __float2bfloat16(w - __bfloat162float(h));
    d_Wt[n * 136 + k]          = *(unsigned short*)&h;
    d_Wt[17408 + n * 136 + k]  = *(unsigned short*)&l;
}

// ---------------- K1: gx[b] += x[node]  (also warms x into L2) ----------------
__global__ void k_gx(const float* __restrict__ x, const void* __restrict__ bat,
                     long long N) {
    long long idx = (long long)blockIdx.x * blockDim.x + threadIdx.x;
    if (idx >= N * 16) return;
    long long node = idx >> 4;
    int q = (int)(idx & 15);
    int g = (int)ldix(bat, node, d_f_b64);
    float4 v = ((const float4*)x)[node * 16 + q];
    red4(d_gx + (long long)g * 64 + q * 4, v);
}

// ---------------- K2: persistent pipelined mma.sync edge kernel ----------------
// Tile = 128 edges x 128 cols. 8 warps: warp grid 4m x 2n, warp tile 32e x 64j.
// Pipeline: cp.async gathers for tile t+1 overlap MMA+epilogue of tile t.
__global__ __launch_bounds__(256, 1)
void k_edge(const float* __restrict__ x, const void* __restrict__ eidx,
            const float* __restrict__ ea, const void* __restrict__ bat,
            const float* __restrict__ b1a, long long E, int ntiles) {
    extern __shared__ char smem[];
    const uint32_t sb = smem_u32(smem);
    const int tid = threadIdx.x, wid = tid >> 5, lane = tid & 31;
    const int e64 = d_f_e64, b64 = d_f_b64;
    const int wm = wid & 3, wn = wid >> 2;
    const int rowb = wm * 32, colb = wn * 64;

    // one-time: W tiles (69.6KB) + smem cnt zero
    {
        const uint4* wsrc = (const uint4*)d_Wt;
        uint4* wdst = (uint4*)(smem + S_W);
        for (int i = tid; i < 4352; i += 256) wdst[i] = wsrc[i];
    }
    for (int i = tid; i < MAXB; i += 256) *(int*)(smem + S_CNT + i * 4) = 0;

    // bias for this lane's columns (fixed across tiles)
    float bb0[8], bb1[8];
    #pragma unroll
    for (int ni = 0; ni < 8; ++ni) {
        int colp = colb + ni * 8 + 2 * (lane & 3);
        bb0[ni] = b1a[colp];
        bb1[ni] = b1a[colp + 1];
    }
    float q0[8], q1[8];
    #pragma unroll
    for (int ni = 0; ni < 8; ++ni) { q0[ni] = 0.f; q1[ni] = 0.f; }

    // gather/convert lane mapping: 2 edges per warp-iter, 16 lanes per row-half
    const int eSub = lane >> 4;             // 0,1
    const int c4   = lane & 15;             // float4 index within 64-float half
    // ldmatrix lane-address components
    const int arow = lane & 15;
    const int akof = (lane >> 4) * 16;
    const int brow = (lane & 7) + ((lane & 16) >> 1);
    const int bkof = ((lane >> 3) & 1) * 16;
    const int quad = 4 * ((lane & 3) >> 1);

    const int gstride = gridDim.x;

    // ---- prologue: indices + cp.async gathers for first tile (parity 0) ----
    {
        long long e0 = (long long)blockIdx.x * 128;
        if (tid < 128) {
            long long e = e0 + tid;
            int r = 0, g = 0;
            if (e < E) {
                r = (int)ldix(eidx, e, e64);
                long long c2 = ldix(eidx, E + e, e64);
                g = (int)ldix(bat, c2, b64);
            }
            *(int*)(smem + S_SR0 + tid * 4) = r;
            *(int*)(smem + S_SG0 + tid * 4) = g;
        }
        __syncthreads();
        #pragma unroll
        for (int i = 0; i < 8; ++i) {
            int e = wid * 16 + i * 2 + eSub;
            int r = *(const int*)(smem + S_SR0 + e * 4);
            long long eg = e0 + e; if (eg >= E) eg = 0;
            cpa16(sb + S_RAW + (uint32_t)e * 528 + c4 * 16,       x + (size_t)r * 64 + c4 * 4);
            cpa16(sb + S_RAW + (uint32_t)e * 528 + 256 + c4 * 16, ea + eg * 64 + c4 * 4);
        }
        asm volatile("cp.async.commit_group;" ::: "memory");
    }

    for (int t = blockIdx.x; t < ntiles; t += gstride) {
        const long long e0 = (long long)t * 128;
        const int p = ((t / gstride) & 1);
        const uint32_t sgp  = (p ? S_SG1 : S_SG0);
        const uint32_t sgn  = (p ? S_SG0 : S_SG1);
        const uint32_t srn  = (p ? S_SR0 : S_SR1);

        asm volatile("cp.async.wait_group 0;" ::: "memory");
        __syncthreads();                       // raw(t) ready; prior epilogue done

        // ---- convert raw fp32 -> bf16 hi/lo (coalesced) ----
        #pragma unroll
        for (int i = 0; i < 8; ++i) {
            int e = wid * 16 + i * 2 + eSub;
            bool ok = (e0 + e) < E;
            const char* rp = smem + S_RAW + (size_t)e * 528;
            char* ah = smem + S_A + (size_t)e * 272;
            char* al = ah + 34816;
            #pragma unroll
            for (int h = 0; h < 2; ++h) {
                float4 v = ok ? *(const float4*)(rp + h * 256 + c4 * 16)
                              : make_float4(0.f, 0.f, 0.f, 0.f);
                __nv_bfloat162 h01 = __floats2bfloat162_rn(v.x, v.y);
                __nv_bfloat162 h23 = __floats2bfloat162_rn(v.z, v.w);
                float lx = v.x - __bfloat162float(h01.x);
                float ly = v.y - __bfloat162float(h01.y);
                float lz = v.z - __bfloat162float(h23.x);
                float lw = v.w - __bfloat162float(h23.y);
                __nv_bfloat162 l01 = __floats2bfloat162_rn(lx, ly);
                __nv_bfloat162 l23 = __floats2bfloat162_rn(lz, lw);
                *(uint2*)(ah + h * 128 + c4 * 8) = make_uint2(*(uint32_t*)&h01, *(uint32_t*)&h23);
                *(uint2*)(al + h * 128 + c4 * 8) = make_uint2(*(uint32_t*)&l01, *(uint32_t*)&l23);
            }
        }

        // ---- indices for next tile (ping-pong buffer) ----
        const long long tn = (long long)t + gstride;
        const bool have_next = tn < ntiles;
        if (have_next && tid < 128) {
            long long e = tn * 128 + tid;
            int r = 0, g = 0;
            if (e < E) {
                r = (int)ldix(eidx, e, e64);
                long long c2 = ldix(eidx, E + e, e64);
                g = (int)ldix(bat, c2, b64);
            }
            *(int*)(smem + srn + tid * 4) = r;
            *(int*)(smem + sgn + tid * 4) = g;
        }
        if (tid < 128 && (e0 + tid) < E)
            atomicAdd((int*)(smem + S_CNT + (*(int*)(smem + sgp + tid * 4)) * 4), 1);
        __syncthreads();                       // Abf ready; next indices visible

        // ---- issue cp.async gathers for next tile (overlaps MMA+epilogue) ----
        if (have_next) {
            long long en0 = tn * 128;
            #pragma unroll
            for (int i = 0; i < 8; ++i) {
                int e = wid * 16 + i * 2 + eSub;
                int r = *(const int*)(smem + srn + e * 4);
                long long eg = en0 + e; if (eg >= E) eg = 0;
                cpa16(sb + S_RAW + (uint32_t)e * 528 + c4 * 16,       x + (size_t)r * 64 + c4 * 4);
                cpa16(sb + S_RAW + (uint32_t)e * 528 + 256 + c4 * 16, ea + eg * 64 + c4 * 4);
            }
            asm volatile("cp.async.commit_group;" ::: "memory");
        }

        // ---- MMA mainloop ----
        float c[2][8][4];
        #pragma unroll
        for (int mi = 0; mi < 2; ++mi)
            #pragma unroll
            for (int ni = 0; ni < 8; ++ni)
                #pragma unroll
                for (int j = 0; j < 4; ++j) c[mi][ni][j] = 0.f;

        #pragma unroll
        for (int kk = 0; kk < 8; ++kk) {
            uint32_t ah[2][4], al_[2][4];
            #pragma unroll
            for (int mi = 0; mi < 2; ++mi) {
                uint32_t aaddr = sb + S_A + (uint32_t)(rowb + mi * 16 + arow) * 272
                                 + kk * 32 + akof;
                LDSM4(ah[mi], aaddr);
                LDSM4(al_[mi], aaddr + 34816u);
            }
            #pragma unroll
            for (int np = 0; np < 4; ++np) {
                uint32_t baddr = sb + S_W + (uint32_t)(colb + np * 16 + brow) * 272
                                 + kk * 32 + bkof;
                uint32_t bh[4];
                LDSM4(bh, baddr);
                #pragma unroll
                for (int mi = 0; mi < 2; ++mi) {
                    MMA16816(c[mi][np * 2 + 0], ah[mi],  bh[0], bh[1]);
                    MMA16816(c[mi][np * 2 + 1], ah[mi],  bh[2], bh[3]);
                    MMA16816(c[mi][np * 2 + 0], al_[mi], bh[0], bh[1]);
                    MMA16816(c[mi][np * 2 + 1], al_[mi], bh[2], bh[3]);
                }
                uint32_t bl[4];
                LDSM4(bl, baddr + 34816u);
                #pragma unroll
                for (int mi = 0; mi < 2; ++mi) {
                    MMA16816(c[mi][np * 2 + 0], ah[mi], bl[0], bl[1]);
                    MMA16816(c[mi][np * 2 + 1], ah[mi], bl[2], bl[3]);
                }
            }
        }

        // ---- epilogue: bias + leaky + Q accum + pairwise shuffle + red4 scatter ----
        #pragma unroll
        for (int mi = 0; mi < 2; ++mi) {
            int rA = rowb + mi * 16 + (lane >> 2);
            int rB = rA + 8;
            bool vA = (e0 + rA) < E, vB = (e0 + rB) < E;
            int gA = *(const int*)(smem + sgp + rA * 4);
            int gB = *(const int*)(smem + sgp + rB * 4);
            #pragma unroll
            for (int ni = 0; ni < 8; ++ni) {
                float a0 = leaky(c[mi][ni][0] + bb0[ni]);
                float a1 = leaky(c[mi][ni][1] + bb1[ni]);
                float a2 = leaky(c[mi][ni][2] + bb0[ni]);
                float a3 = leaky(c[mi][ni][3] + bb1[ni]);
                if (vA) { q0[ni] += a0 * a0; q1[ni] += a1 * a1; }
                if (vB) { q0[ni] += a2 * a2; q1[ni] += a3 * a3; }
                float x0 = __shfl_xor_sync(0xffffffffu, a0, 1);
                float x1 = __shfl_xor_sync(0xffffffffu, a1, 1);
                float x2 = __shfl_xor_sync(0xffffffffu, a2, 1);
                float x3 = __shfl_xor_sync(0xffffffffu, a3, 1);
                int col = colb + ni * 8 + quad;
                if ((lane & 1) == 0) {
                    if (vA) red4(d_A + (size_t)gA * 128 + col, make_float4(a0, a1, x0, x1));
                } else {
                    if (vB) red4(d_A + (size_t)gB * 128 + col, make_float4(x2, x3, a2, a3));
                }
            }
        }
    }

    // ---- flush Q (cross-lane reduce within col groups, then global atomics) ----
    #pragma unroll
    for (int ni = 0; ni < 8; ++ni) {
        #pragma unroll
        for (int o = 4; o < 32; o <<= 1) {
            q0[ni] += __shfl_xor_sync(0xffffffffu, q0[ni], o);
            q1[ni] += __shfl_xor_sync(0xffffffffu, q1[ni], o);
        }
    }
    if (lane < 4) {
        #pragma unroll
        for (int ni = 0; ni < 8; ++ni) {
            int colp = colb + ni * 8 + 2 * lane;
            atomicAdd(&d_Q[colp],     q0[ni]);
            atomicAdd(&d_Q[colp + 1], q1[ni]);
        }
    }
    // ---- flush edge counts ----
    __syncthreads();
    for (int i = tid; i < MAXB; i += 256) {
        int v = *(const int*)(smem + S_CNT + i * 4);
        if (v) atomicAdd(&d_cnt[i], v);
    }
}

// ---------------- K3: BN1a stats (parallel over 128 cols) ----------------
__global__ void k_stats(const float* __restrict__ g1a, const float* __restrict__ be1a,
                        float Ef, int B) {
    __shared__ float red_s[128];
    int j = blockIdx.x;
    float s = 0.f;
    for (int b = threadIdx.x; b < B; b += 128) s += d_A[b * 128 + j];
    red_s[threadIdx.x] = s;
    __syncthreads();
    for (int o = 64; o; o >>= 1) {
        if (threadIdx.x < o) red_s[threadIdx.x] += red_s[threadIdx.x + o];
        __syncthreads();
    }
    if (threadIdx.x == 0) {
        float m = red_s[0] / Ef;
        float v = d_Q[j] / Ef - m * m;
        float sc = g1a[j] * rsqrtf(v + EPS);
        d_s1[j] = sc;
        d_t1[j] = be1a[j] - m * sc;
    }
}

// ---------------- K3.5: t2 = t1 @ W2a + b2a ----------------
__global__ void k_prep2(const float* __restrict__ W2a, const float* __restrict__ b2a) {
    __shared__ float st[128];
    int j = threadIdx.x;
    st[j] = d_t1[j];
    __syncthreads();
    float a = b2a[j];
    #pragma unroll 8
    for (int k = 0; k < 128; ++k) a += st[k] * W2a[k * 128 + j];
    d_t2[j] = a;
}

// ---------------- K4: ga + first graph layer + stats ----------------
__global__ void k_g1(const float* __restrict__ W2a,
                     const float* __restrict__ W1b, const float* __restrict__ b1b) {
    __shared__ float sAs[128], sga[128], sgx[64];
    int b = blockIdx.x, j = threadIdx.x;
    sAs[j] = d_A[b * 128 + j] * d_s1[j];
    if (j < 64) sgx[j] = d_gx[b * 64 + j];
    __syncthreads();
    float cf = (float)d_cnt[b];
    float ga = d_t2[j] * cf;
    #pragma unroll 8
    for (int k = 0; k < 128; ++k) ga += sAs[k] * W2a[k * 128 + j];
    sga[j] = ga;
    __syncthreads();
    float z = b1b[j];
    #pragma unroll 8
    for (int i = 0; i < 64; ++i)  z += sgx[i] * W1b[i * 128 + j];
    #pragma unroll 8
    for (int i = 0; i < 128; ++i) z += sga[i] * W1b[(64 + i) * 128 + j];
    float a = leaky(z);
    d_a1[b * 128 + j] = a;
    atomicAdd(&d_S1[j], a);
    atomicAdd(&d_Q1[j], a * a);
}

// ---------------- K5: BN1b + second graph layer + stats ----------------
__global__ void k_g2(const float* __restrict__ W2b, const float* __restrict__ b2b,
                     const float* __restrict__ g1b, const float* __restrict__ be1b,
                     float Bf) {
    __shared__ float sh[128];
    int b = blockIdx.x, j = threadIdx.x;
    float m = d_S1[j] / Bf;
    float v = d_Q1[j] / Bf - m * m;
    float s = g1b[j] * rsqrtf(v + EPS);
    float t = be1b[j] - m * s;
    sh[j] = d_a1[b * 128 + j] * s + t;
    __syncthreads();
    float z = b2b[j];
    #pragma unroll 8
    for (int k = 0; k < 128; ++k) z += sh[k] * W2b[k * 128 + j];
    float a = leaky(z);
    d_a2[b * 128 + j] = a;
    atomicAdd(&d_S2[j], a);
    atomicAdd(&d_Q2[j], a * a);
}

// ---------------- K6: BN2b + output layer ----------------
__global__ void k_g3(const float* __restrict__ W3b, const float* __restrict__ b3b,
                     const float* __restrict__ g2b, const float* __restrict__ be2b,
                     float Bf, float* __restrict__ out) {
    __shared__ float sh[128];
    int b = blockIdx.x, j = threadIdx.x;
    float m = d_S2[j] / Bf;
    float v = d_Q2[j] / Bf - m * m;
    float s = g2b[j] * rsqrtf(v + EPS);
    float t = be2b[j] - m * s;
    sh[j] = d_a2[b * 128 + j] * s + t;
    __syncthreads();
    float z = b3b[j];
    #pragma unroll 8
    for (int k = 0; k < 128; ++k) z += sh[k] * W3b[k * 128 + j];
    out[b * 128 + j] = z;
}

// ---------------- launch ----------------
extern "C" void kernel_launch(void* const* d_in, const int* in_sizes, int n_in,
                              void* d_out, int out_size) {
    const float* x    = (const float*)d_in[0];
    const void*  ei   = d_in[1];
    const float* ea   = (const float*)d_in[2];
    const void*  bat  = d_in[4];
    const float* W1a  = (const float*)d_in[5];
    const float* b1a  = (const float*)d_in[6];
    const float* g1a  = (const float*)d_in[7];
    const float* be1a = (const float*)d_in[8];
    const float* W2a  = (const float*)d_in[9];
    const float* b2a  = (const float*)d_in[10];
    const float* W1b  = (const float*)d_in[11];
    const float* b1b  = (const float*)d_in[12];
    const float* g1b  = (const float*)d_in[13];
    const float* be1b = (const float*)d_in[14];
    const float* W2b  = (const float*)d_in[15];
    const float* b2b  = (const float*)d_in[16];
    const float* g2b  = (const float*)d_in[17];
    const float* be2b = (const float*)d_in[18];
    const float* W3b  = (const float*)d_in[19];
    const float* b3b  = (const float*)d_in[20];

    long long N = (long long)in_sizes[0] / 64;
    long long E = (long long)in_sizes[2] / 64;
    int B = in_sizes[3];
    if (B > MAXB) B = MAXB;

    static int smem_set = 0;
    if (!smem_set) {
        cudaFuncSetAttribute(k_edge, cudaFuncAttributeMaxDynamicSharedMemorySize, SMEM_TOT);
        smem_set = 1;
    }

    k_init<<<256, 256>>>(ei, bat, 2 * E, N);
    k_wprep<<<64, 256>>>(W1a);

    int gridN = (int)((N * 16 + 255) / 256);
    k_gx<<<gridN, 256>>>(x, bat, N);           // also warms x into L2 for gathers

    int ntiles = (int)((E + 127) / 128);
    int grid = ntiles < 148 ? ntiles : 148;
    k_edge<<<grid, 256, SMEM_TOT>>>(x, ei, ea, bat, b1a, E, ntiles);

    k_stats<<<128, 128>>>(g1a, be1a, (float)E, B);
    k_prep2<<<1, 128>>>(W2a, b2a);
    k_g1<<<B, 128>>>(W2a, W1b, b1b);
    k_g2<<<B, 128>>>(W2b, b2b, g1b, be1b, (float)B);
    k_g3<<<B, 128>>>(W3b, b3b, g2b, be2b, (float)B, (float*)d_out);
}

// round 11
// speedup vs baseline: 1.7967x; 1.1236x over previous
#include <cuda_runtime.h>
#include <cuda_bf16.h>
#include <cstdint>

#define MAXB  1024
#define EMAX  (1 << 20)
#define EPS   1e-5f
#define SLOPE 0.01f

// ---------------- static device scratch (no allocations allowed) ----------------
__device__ __align__(16) float d_A [MAXB * 128];
__device__ __align__(16) float d_gx[MAXB * 64];
__device__            int   d_cnt[MAXB];
__device__ __align__(16) float d_Q [128];
__device__ __align__(16) float d_s1[128], d_t1[128], d_t2[128];
__device__ __align__(16) float d_S1[128], d_Q1[128], d_S2[128], d_Q2[128];
__device__ __align__(16) float d_a1[MAXB * 128], d_a2[MAXB * 128];
__device__ __align__(16) unsigned short d_Wt[34816]; // W^T bf16 hi[128][136], lo[128][136]
__device__ __align__(16) int4  d_se[EMAX];           // sorted edges: {row, g, e_orig, 0}
__device__            int   d_hist[MAXB], d_cur[MAXB];
__device__            int   d_bar[8];
__device__            int   d_f_e64, d_f_b64;

// ---------------- smem layout of k_edge ----------------
#define S_IDX0  0
#define S_IDX1  2048
#define S_CB    4096
#define S_W     6144        // Whi [128][272B] then Wlo  (69632)
#define S_A     75776       // bf16 tiles (69632); reused as f32 dump [128][132]
#define S_RAW   145408      // raw fp32 [128][132 floats] (67584)
#define SMEM_TOT 212992

// ---------------- helpers ----------------
__device__ __forceinline__ void red4(float* p, float4 v) {
    asm volatile("red.global.add.v4.f32 [%0], {%1,%2,%3,%4};"
                 :: "l"(p), "f"(v.x), "f"(v.y), "f"(v.z), "f"(v.w) : "memory");
}
__device__ __forceinline__ void redf(float* p, float v) {
    asm volatile("red.global.add.f32 [%0], %1;" :: "l"(p), "f"(v) : "memory");
}
__device__ __forceinline__ long long ldix(const void* p, long long i, int is64) {
    return is64 ? ((const long long*)p)[i] : (long long)((const int*)p)[i];
}
__device__ __forceinline__ float leaky(float z) { return z >= 0.f ? z : SLOPE * z; }
__device__ __forceinline__ uint32_t smem_u32(const void* p) {
    uint32_t a;
    asm("{ .reg .u64 t; cvta.to.shared.u64 t, %1; cvt.u32.u64 %0, t; }" : "=r"(a) : "l"(p));
    return a;
}
__device__ __forceinline__ void cpa16(uint32_t s, const void* g) {
    asm volatile("cp.async.cg.shared.global [%0], [%1], 16;" :: "r"(s), "l"(g) : "memory");
}
#define LDSM4(r, a) \
    asm volatile("ldmatrix.sync.aligned.m8n8.x4.shared.b16 {%0,%1,%2,%3}, [%4];" \
        : "=r"((r)[0]), "=r"((r)[1]), "=r"((r)[2]), "=r"((r)[3]) : "r"(a))
#define MMA16816(c, a, b0, b1) \
    asm volatile("mma.sync.aligned.m16n8k16.row.col.f32.bf16.bf16.f32 " \
        "{%0,%1,%2,%3}, {%4,%5,%6,%7}, {%8,%9}, {%0,%1,%2,%3};" \
        : "+f"((c)[0]), "+f"((c)[1]), "+f"((c)[2]), "+f"((c)[3]) \
        : "r"((a)[0]), "r"((a)[1]), "r"((a)[2]), "r"((a)[3]), "r"(b0), "r"(b1))

__device__ __forceinline__ void gbar(int i, int n) {
    __syncthreads();
    if (threadIdx.x == 0) {
        __threadfence();
        atomicAdd(&d_bar[i], 1);
        while (atomicAdd(&d_bar[i], 0) < n) { __nanosleep(64); }
    }
    __syncthreads();
}

// ---------------- K0: zero scratch + detect index width ----------------
__global__ void k_init(const void* eidx, const void* bat,
                       long long e2w, long long nw) {
    int idx = blockIdx.x * blockDim.x + threadIdx.x;
    int stride = gridDim.x * blockDim.x;
    for (int i = idx; i < MAXB * 128; i += stride) d_A[i] = 0.f;
    for (int i = idx; i < MAXB * 64;  i += stride) d_gx[i] = 0.f;
    for (int i = idx; i < MAXB;       i += stride) d_hist[i] = 0;
    for (int i = idx; i < 128;        i += stride) {
        d_Q[i] = 0.f; d_S1[i] = 0.f; d_Q1[i] = 0.f; d_S2[i] = 0.f; d_Q2[i] = 0.f;
    }
    if (idx < 8) d_bar[idx] = 0;
    if (blockIdx.x == 0 && threadIdx.x < 32) {
        const unsigned* we = (const unsigned*)eidx;
        const unsigned* wb = (const unsigned*)bat;
        int lane = threadIdx.x;
        int nz_e = 0, nz_b = 0;
        long long se = e2w / 64; if (se < 2) se = 2;
        long long sb = nw  / 64; if (sb < 2) sb = 2;
        for (int s = 0; s < 2; ++s) {
            long long k = lane * 2 + s;
            long long pe = (k * se) | 1; if (pe >= e2w) pe = 1;
            long long pb = (k * sb) | 1; if (pb >= nw)  pb = 1;
            if (we[pe] != 0u) nz_e++;
            if (wb[pb] != 0u) nz_b++;
        }
        for (int o = 16; o > 0; o >>= 1) {
            nz_e += __shfl_xor_sync(0xffffffffu, nz_e, o);
            nz_b += __shfl_xor_sync(0xffffffffu, nz_b, o);
        }
        if (lane == 0) {
            d_f_e64 = (nz_e < 8) ? 1 : 0;
            d_f_b64 = (nz_b < 8) ? 1 : 0;
        }
    }
}

// ---------------- K0.5: W1a -> W^T bf16 hi/lo ----------------
__global__ void k_wprep(const float* __restrict__ W1a) {
    int tid = blockIdx.x * blockDim.x + threadIdx.x;
    if (tid >= 16384) return;
    int k = tid >> 7, n = tid & 127;
    float w = W1a[k * 128 + n];
    __nv_bfloat16 h = __float2bfloat16(w);
    __nv_bfloat16 l = __float2bfloat16(w - __bfloat162float(h));
    d_Wt[n * 136 + k]          = *(unsigned short*)&h;
    d_Wt[17408 + n * 136 + k]  = *(unsigned short*)&l;
}

// ---------------- sort pass 1: histogram over graphs ----------------
__global__ void k_hist(const void* __restrict__ ei, const void* __restrict__ bat,
                       long long E) {
    __shared__ int lh[MAXB];
    int tid = threadIdx.x;
    for (int i = tid; i < MAXB; i += blockDim.x) lh[i] = 0;
    __syncthreads();
    int e64 = d_f_e64, b64 = d_f_b64;
    long long idx = (long long)blockIdx.x * blockDim.x + tid;
    long long stride = (long long)gridDim.x * blockDim.x;
    for (long long e = idx; e < E; e += stride) {
        long long c = ldix(ei, E + e, e64);
        int g = (int)ldix(bat, c, b64);
        atomicAdd(&lh[g], 1);
    }
    __syncthreads();
    for (int i = tid; i < MAXB; i += blockDim.x)
        if (lh[i]) atomicAdd(&d_hist[i], lh[i]);
}

// ---------------- sort pass 2: exclusive scan (one block, 1024 thr) ----------------
__global__ void k_scan() {
    __shared__ int s[MAXB];
    int t = threadIdx.x;
    int v = d_hist[t];
    s[t] = v;
    __syncthreads();
    for (int o = 1; o < MAXB; o <<= 1) {
        int u = (t >= o) ? s[t - o] : 0;
        __syncthreads();
        s[t] += u;
        __syncthreads();
    }
    d_cur[t] = s[t] - v;
    d_cnt[t] = v;
}

// ---------------- sort pass 3: scatter (block-privatized cursors) ----------------
#define CH 2048
__global__ void k_scatter(const void* __restrict__ ei, const void* __restrict__ bat,
                          long long E) {
    __shared__ int sg_[CH], sr_[CH];
    __shared__ int lh[MAXB], lbase[MAXB];
    int tid = threadIdx.x;
    long long e0 = (long long)blockIdx.x * CH;
    for (int i = tid; i < MAXB; i += 256) lh[i] = 0;
    __syncthreads();
    int e64 = d_f_e64, b64 = d_f_b64;
    for (int i = tid; i < CH; i += 256) {
        long long e = e0 + i;
        if (e < E) {
            int r = (int)ldix(ei, e, e64);
            long long c = ldix(ei, E + e, e64);
            int g = (int)ldix(bat, c, b64);
            sr_[i] = r; sg_[i] = g;
            atomicAdd(&lh[g], 1);
        } else sg_[i] = -1;
    }
    __syncthreads();
    for (int g = tid; g < MAXB; g += 256)
        if (lh[g]) lbase[g] = atomicAdd(&d_cur[g], lh[g]);
    __syncthreads();
    for (int g = tid; g < MAXB; g += 256) lh[g] = 0;
    __syncthreads();
    for (int i = tid; i < CH; i += 256) {
        int g = sg_[i];
        if (g >= 0) {
            int o = atomicAdd(&lh[g], 1);
            d_se[lbase[g] + o] = make_int4(sr_[i], g, (int)(e0 + i), 0);
        }
    }
}

// ---------------- K1: gx[b] += x[node] (warms x into L2) ----------------
__global__ void k_gx(const float* __restrict__ x, const void* __restrict__ bat,
                     long long N) {
    long long idx = (long long)blockIdx.x * blockDim.x + threadIdx.x;
    if (idx >= N * 16) return;
    long long node = idx >> 4;
    int q = (int)(idx & 15);
    int g = (int)ldix(bat, node, d_f_b64);
    float4 v = ((const float4*)x)[node * 16 + q];
    red4(d_gx + (long long)g * 64 + q * 4, v);
}

// ---------------- K2: persistent pipelined mma.sync edge kernel (sorted) ------
__global__ __launch_bounds__(256, 1)
void k_edge(const float* __restrict__ x, const float* __restrict__ ea,
            const float* __restrict__ b1a, long long E, int ntiles) {
    extern __shared__ char smem[];
    const uint32_t sb = smem_u32(smem);
    const int tid = threadIdx.x, wid = tid >> 5, lane = tid & 31;
    const int wm = wid & 3, wn = wid >> 2;
    const int rowb = wm * 32, colb = wn * 64;

    // one-time: W tiles
    {
        const uint4* wsrc = (const uint4*)d_Wt;
        uint4* wdst = (uint4*)(smem + S_W);
        for (int i = tid; i < 4352; i += 256) wdst[i] = wsrc[i];
    }

    // bias for this lane's columns
    float bb0[8], bb1[8];
    #pragma unroll
    for (int ni = 0; ni < 8; ++ni) {
        int colp = colb + ni * 8 + 2 * (lane & 3);
        bb0[ni] = b1a[colp];
        bb1[ni] = b1a[colp + 1];
    }
    // per-column Q accumulator (scan layout)
    const int mycol = tid & 127, myhalf = tid >> 7;
    float qacc = 0.f;

    const int eSub = lane >> 4;
    const int c4   = lane & 15;
    const int arow = lane & 15;
    const int akof = (lane >> 4) * 16;
    const int brow = (lane & 7) + ((lane & 16) >> 1);
    const int bkof = ((lane >> 3) & 1) * 16;
    const int gstride = gridDim.x;

    // ---- prologue ----
    {
        long long e0 = (long long)blockIdx.x * 128;
        if (tid < 128) {
            long long e = e0 + tid;
            int4 v = (e < E) ? d_se[e] : make_int4(0, -1, 0, 0);
            *(int4*)(smem + S_IDX0 + tid * 16) = v;
        }
        __syncthreads();
        #pragma unroll
        for (int i = 0; i < 8; ++i) {
            int e = wid * 16 + i * 2 + eSub;
            int4 iv = *(const int4*)(smem + S_IDX0 + e * 16);
            cpa16(sb + S_RAW + (uint32_t)e * 528 + c4 * 16,       x + (size_t)iv.x * 64 + c4 * 4);
            cpa16(sb + S_RAW + (uint32_t)e * 528 + 256 + c4 * 16, ea + (size_t)iv.z * 64 + c4 * 4);
        }
        asm volatile("cp.async.commit_group;" ::: "memory");
    }

    for (int t = blockIdx.x; t < ntiles; t += gstride) {
        const int p = ((t / gstride) & 1);
        const uint32_t sip = (p ? S_IDX1 : S_IDX0);
        const uint32_t sin = (p ? S_IDX0 : S_IDX1);

        asm volatile("cp.async.wait_group 0;" ::: "memory");
        __syncthreads();                       // raw(t) ready; scan(t-1) done with S_A

        // ---- convert raw fp32 -> bf16 hi/lo ----
        #pragma unroll
        for (int i = 0; i < 8; ++i) {
            int e = wid * 16 + i * 2 + eSub;
            const char* rp = smem + S_RAW + (size_t)e * 528;
            char* ah = smem + S_A + (size_t)e * 272;
            char* al = ah + 34816;
            #pragma unroll
            for (int h = 0; h < 2; ++h) {
                float4 v = *(const float4*)(rp + h * 256 + c4 * 16);
                __nv_bfloat162 h01 = __floats2bfloat162_rn(v.x, v.y);
                __nv_bfloat162 h23 = __floats2bfloat162_rn(v.z, v.w);
                float lx = v.x - __bfloat162float(h01.x);
                float ly = v.y - __bfloat162float(h01.y);
                float lz = v.z - __bfloat162float(h23.x);
                float lw = v.w - __bfloat162float(h23.y);
                __nv_bfloat162 l01 = __floats2bfloat162_rn(lx, ly);
                __nv_bfloat162 l23 = __floats2bfloat162_rn(lz, lw);
                *(uint2*)(ah + h * 128 + c4 * 8) = make_uint2(*(uint32_t*)&h01, *(uint32_t*)&h23);
                *(uint2*)(al + h * 128 + c4 * 8) = make_uint2(*(uint32_t*)&l01, *(uint32_t*)&l23);
            }
        }

        // ---- indices for next tile ----
        const long long tn = (long long)t + gstride;
        const bool have_next = tn < ntiles;
        if (have_next && tid < 128) {
            long long e = tn * 128 + tid;
            int4 v = (e < E) ? d_se[e] : make_int4(0, -1, 0, 0);
            *(int4*)(smem + sin + tid * 16) = v;
        }
        __syncthreads();

        // ---- issue cp.async for next tile ----
        if (have_next) {
            #pragma unroll
            for (int i = 0; i < 8; ++i) {
                int e = wid * 16 + i * 2 + eSub;
                int4 iv = *(const int4*)(smem + sin + e * 16);
                cpa16(sb + S_RAW + (uint32_t)e * 528 + c4 * 16,       x + (size_t)iv.x * 64 + c4 * 4);
                cpa16(sb + S_RAW + (uint32_t)e * 528 + 256 + c4 * 16, ea + (size_t)iv.z * 64 + c4 * 4);
            }
            asm volatile("cp.async.commit_group;" ::: "memory");
        }

        // ---- MMA mainloop ----
        float c[2][8][4];
        #pragma unroll
        for (int mi = 0; mi < 2; ++mi)
            #pragma unroll
            for (int ni = 0; ni < 8; ++ni)
                #pragma unroll
                for (int j = 0; j < 4; ++j) c[mi][ni][j] = 0.f;

        #pragma unroll
        for (int kk = 0; kk < 8; ++kk) {
            uint32_t ah[2][4], al_[2][4];
            #pragma unroll
            for (int mi = 0; mi < 2; ++mi) {
                uint32_t aaddr = sb + S_A + (uint32_t)(rowb + mi * 16 + arow) * 272
                                 + kk * 32 + akof;
                LDSM4(ah[mi], aaddr);
                LDSM4(al_[mi], aaddr + 34816u);
            }
            #pragma unroll
            for (int np = 0; np < 4; ++np) {
                uint32_t baddr = sb + S_W + (uint32_t)(colb + np * 16 + brow) * 272
                                 + kk * 32 + bkof;
                uint32_t bh[4];
                LDSM4(bh, baddr);
                #pragma unroll
                for (int mi = 0; mi < 2; ++mi) {
                    MMA16816(c[mi][np * 2 + 0], ah[mi],  bh[0], bh[1]);
                    MMA16816(c[mi][np * 2 + 1], ah[mi],  bh[2], bh[3]);
                    MMA16816(c[mi][np * 2 + 0], al_[mi], bh[0], bh[1]);
                    MMA16816(c[mi][np * 2 + 1], al_[mi], bh[2], bh[3]);
                }
                uint32_t bl[4];
                LDSM4(bl, baddr + 34816u);
                #pragma unroll
                for (int mi = 0; mi < 2; ++mi) {
                    MMA16816(c[mi][np * 2 + 0], ah[mi], bl[0], bl[1]);
                    MMA16816(c[mi][np * 2 + 1], ah[mi], bl[2], bl[3]);
                }
            }
        }
        __syncthreads();                 // all warps done reading A bf16

        // ---- dump bias+leaky activations to smem (S_A as f32 [128][132]) ----
        float* dump = (float*)(smem + S_A);
        #pragma unroll
        for (int mi = 0; mi < 2; ++mi) {
            int rA = rowb + mi * 16 + (lane >> 2);
            int rB = rA + 8;
            #pragma unroll
            for (int ni = 0; ni < 8; ++ni) {
                int colp = colb + ni * 8 + 2 * (lane & 3);
                float2 vA = make_float2(leaky(c[mi][ni][0] + bb0[ni]),
                                        leaky(c[mi][ni][1] + bb1[ni]));
                float2 vB = make_float2(leaky(c[mi][ni][2] + bb0[ni]),
                                        leaky(c[mi][ni][3] + bb1[ni]));
                *(float2*)(dump + rA * 132 + colp) = vA;
                *(float2*)(dump + rB * 132 + colp) = vB;
            }
        }
        __syncthreads();

        // ---- column scan: sum 64 edges per (col, half); flush by graph ----
        int g0   = *(const int*)(smem + sip + 4);
        int g127 = *(const int*)(smem + sip + 127 * 16 + 4);
        bool mono = (g0 == g127) && (g0 >= 0);
        if (mono) {
            float acc = 0.f;
            const float* dp = dump + (myhalf * 64) * 132 + mycol;
            #pragma unroll 8
            for (int e = 0; e < 64; ++e) {
                float v = dp[e * 132];
                acc += v;
                qacc += v * v;
            }
            float* cb = (float*)(smem + S_CB);
            cb[myhalf * 128 + mycol] = acc;
            __syncthreads();
            if (tid < 128) cb[tid] = cb[tid] + cb[128 + tid];
            __syncthreads();
            if (tid < 32) {
                float4 vv = *(const float4*)((float*)(smem + S_CB) + tid * 4);
                red4(d_A + (size_t)g0 * 128 + tid * 4, vv);
            }
        } else {
            float acc = 0.f;
            int curg = -1;
            const float* dp = dump + (myhalf * 64) * 132 + mycol;
            const char* sgp = smem + sip + (myhalf * 64) * 16 + 4;
            for (int e = 0; e < 64; ++e) {
                int gg = *(const int*)(sgp + e * 16);
                float v = dp[e * 132];
                if (gg != curg) {
                    if (curg >= 0) redf(d_A + (size_t)curg * 128 + mycol, acc);
                    acc = 0.f;
                    curg = gg;
                }
                if (gg >= 0) { acc += v; qacc += v * v; }
            }
            if (curg >= 0) redf(d_A + (size_t)curg * 128 + mycol, acc);
        }
    }

    // ---- flush per-column Q ----
    atomicAdd(&d_Q[mycol], qacc);
}

// ---------------- fused tail: stats -> t2 -> g1 -> g2 -> g3 ----------------
__global__ void k_tail(const float* __restrict__ g1a, const float* __restrict__ be1a,
                       const float* __restrict__ b2a, const float* __restrict__ W2a,
                       const float* __restrict__ W1b, const float* __restrict__ b1b,
                       const float* __restrict__ W2b, const float* __restrict__ b2b,
                       const float* __restrict__ g1b, const float* __restrict__ be1b,
                       const float* __restrict__ W3b, const float* __restrict__ b3b,
                       const float* __restrict__ g2b, const float* __restrict__ be2b,
                       float Ef, float Bf, int B, int ngrid,
                       float* __restrict__ out) {
    __shared__ float sh1[128], sh2[128], sgx[64];
    int blk = blockIdx.x, tid = threadIdx.x;

    // phase 0: BN1a stats per column
    if (blk < 128) {
        float s = 0.f;
        for (int b = tid; b < B; b += 128) s += d_A[b * 128 + blk];
        sh1[tid] = s;
        __syncthreads();
        for (int o = 64; o; o >>= 1) {
            if (tid < o) sh1[tid] += sh1[tid + o];
            __syncthreads();
        }
        if (tid == 0) {
            float m = sh1[0] / Ef;
            float v = d_Q[blk] / Ef - m * m;
            float sc = g1a[blk] * rsqrtf(v + EPS);
            d_s1[blk] = sc;
            d_t1[blk] = be1a[blk] - m * sc;
        }
    }
    gbar(0, ngrid);

    // phase 1: t2 = t1 @ W2a + b2a
    if (blk < 128) {
        sh1[tid] = d_t1[tid] * W2a[tid * 128 + blk];
        __syncthreads();
        for (int o = 64; o; o >>= 1) {
            if (tid < o) sh1[tid] += sh1[tid + o];
            __syncthreads();
        }
        if (tid == 0) d_t2[blk] = sh1[0] + b2a[blk];
    }
    gbar(1, ngrid);

    // phase 2: g1
    if (blk < B) {
        int b = blk, j = tid;
        sh1[j] = d_A[b * 128 + j] * d_s1[j];
        if (j < 64) sgx[j] = d_gx[b * 64 + j];
        __syncthreads();
        float cf = (float)d_cnt[b];
        float ga = d_t2[j] * cf;
        #pragma unroll 8
        for (int k = 0; k < 128; ++k) ga += sh1[k] * W2a[k * 128 + j];
        sh2[j] = ga;
        __syncthreads();
        float z = b1b[j];
        #pragma unroll 8
        for (int i = 0; i < 64; ++i)  z += sgx[i] * W1b[i * 128 + j];
        #pragma unroll 8
        for (int i = 0; i < 128; ++i) z += sh2[i] * W1b[(64 + i) * 128 + j];
        float a = leaky(z);
        d_a1[b * 128 + j] = a;
        atomicAdd(&d_S1[j], a);
        atomicAdd(&d_Q1[j], a * a);
    }
    gbar(2, ngrid);

    // phase 3: g2
    if (blk < B) {
        int b = blk, j = tid;
        float m = d_S1[j] / Bf;
        float v = d_Q1[j] / Bf - m * m;
        float s = g1b[j] * rsqrtf(v + EPS);
        float tt = be1b[j] - m * s;
        sh1[j] = d_a1[b * 128 + j] * s + tt;
        __syncthreads();
        float z = b2b[j];
        #pragma unroll 8
        for (int k = 0; k < 128; ++k) z += sh1[k] * W2b[k * 128 + j];
        float a = leaky(z);
        d_a2[b * 128 + j] = a;
        atomicAdd(&d_S2[j], a);
        atomicAdd(&d_Q2[j], a * a);
        __syncthreads();
    }
    gbar(3, ngrid);

    // phase 4: g3
    if (blk < B) {
        int b = blk, j = tid;
        float m = d_S2[j] / Bf;
        float v = d_Q2[j] / Bf - m * m;
        float s = g2b[j] * rsqrtf(v + EPS);
        float tt = be2b[j] - m * s;
        sh1[j] = d_a2[b * 128 + j] * s + tt;
        __syncthreads();
        float z = b3b[j];
        #pragma unroll 8
        for (int k = 0; k < 128; ++k) z += sh1[k] * W3b[k * 128 + j];
        out[b * 128 + j] = z;
    }
}

// ---------------- launch ----------------
extern "C" void kernel_launch(void* const* d_in, const int* in_sizes, int n_in,
                              void* d_out, int out_size) {
    const float* x    = (const float*)d_in[0];
    const void*  ei   = d_in[1];
    const float* ea   = (const float*)d_in[2];
    const void*  bat  = d_in[4];
    const float* W1a  = (const float*)d_in[5];
    const float* b1a  = (const float*)d_in[6];
    const float* g1a  = (const float*)d_in[7];
    const float* be1a = (const float*)d_in[8];
    const float* W2a  = (const float*)d_in[9];
    const float* b2a  = (const float*)d_in[10];
    const float* W1b  = (const float*)d_in[11];
    const float* b1b  = (const float*)d_in[12];
    const float* g1b  = (const float*)d_in[13];
    const float* be1b = (const float*)d_in[14];
    const float* W2b  = (const float*)d_in[15];
    const float* b2b  = (const float*)d_in[16];
    const float* g2b  = (const float*)d_in[17];
    const float* be2b = (const float*)d_in[18];
    const float* W3b  = (const float*)d_in[19];
    const float* b3b  = (const float*)d_in[20];

    long long N = (long long)in_sizes[0] / 64;
    long long E = (long long)in_sizes[2] / 64;
    int B = in_sizes[3];
    if (B > MAXB) B = MAXB;

    static int smem_set = 0;
    if (!smem_set) {
        cudaFuncSetAttribute(k_edge, cudaFuncAttributeMaxDynamicSharedMemorySize, SMEM_TOT);
        smem_set = 1;
    }

    k_init<<<256, 256>>>(ei, bat, 2 * E, N);
    k_wprep<<<64, 256>>>(W1a);
    k_hist<<<256, 256>>>(ei, bat, E);
    k_scan<<<1, MAXB>>>();
    int gridS = (int)((E + CH - 1) / CH);
    k_scatter<<<gridS, 256>>>(ei, bat, E);

    int gridN = (int)((N * 16 + 255) / 256);
    k_gx<<<gridN, 256>>>(x, bat, N);

    int ntiles = (int)((E + 127) / 128);
    int grid = ntiles < 148 ? ntiles : 148;
    k_edge<<<grid, 256, SMEM_TOT>>>(x, ea, b1a, E, ntiles);

    int ng = B > 128 ? B : 128;
    k_tail<<<ng, 128>>>(g1a, be1a, b2a, W2a, W1b, b1b, W2b, b2b, g1b, be1b,
                        W3b, b3b, g2b, be2b, (float)E, (float)B, B, ng,
                        (float*)d_out);
}

// round 12
// speedup vs baseline: 2.0570x; 1.1449x over previous
#include <cuda_runtime.h>
#include <cuda_fp16.h>
#include <cstdint>

#define MAXB  1024
#define EMAX  (1 << 20)
#define EPS   1e-5f
#define SLOPE 0.01f

// ---------------- static device scratch (no allocations allowed) ----------------
__device__ __align__(16) float d_A [MAXB * 128];
__device__ __align__(16) float d_gx[MAXB * 64];
__device__            int   d_cnt[MAXB];
__device__ __align__(16) float d_Q [128];
__device__ __align__(16) float d_s1[128], d_t1[128], d_t2[128];
__device__ __align__(16) float d_S1[128], d_Q1[128], d_S2[128], d_Q2[128];
__device__ __align__(16) float d_a1[MAXB * 128], d_a2[MAXB * 128];
__device__ __align__(16) unsigned short d_Wt[17408]; // W^T fp16 hi [128][136]
__device__ __align__(16) int4  d_se[EMAX];           // sorted edges {row, g, e_orig, 0}
__device__            int   d_hist[MAXB], d_cur[MAXB];
__device__            int   d_bar[8];
__device__            int   d_f_e64, d_f_b64;

// ---------------- smem layout of k_edge ----------------
#define S_IDX0  0
#define S_IDX1  2048
#define S_CB    4096
#define S_W     6144        // Whi [128][272B] = 34816
#define S_A     40960       // Ahi then Alo (69632); reused as f32 dump [128][132]
#define S_RAW   110592      // raw fp32 [128][132 floats] (67584)
#define SMEM_TOT 178176

// ---------------- helpers ----------------
__device__ __forceinline__ void red4(float* p, float4 v) {
    asm volatile("red.global.add.v4.f32 [%0], {%1,%2,%3,%4};"
                 :: "l"(p), "f"(v.x), "f"(v.y), "f"(v.z), "f"(v.w) : "memory");
}
__device__ __forceinline__ void redf(float* p, float v) {
    asm volatile("red.global.add.f32 [%0], %1;" :: "l"(p), "f"(v) : "memory");
}
__device__ __forceinline__ long long ldix(const void* p, long long i, int is64) {
    return is64 ? ((const long long*)p)[i] : (long long)((const int*)p)[i];
}
__device__ __forceinline__ float leaky(float z) { return z >= 0.f ? z : SLOPE * z; }
__device__ __forceinline__ uint32_t smem_u32(const void* p) {
    uint32_t a;
    asm("{ .reg .u64 t; cvta.to.shared.u64 t, %1; cvt.u32.u64 %0, t; }" : "=r"(a) : "l"(p));
    return a;
}
__device__ __forceinline__ void cpa16(uint32_t s, const void* g) {
    asm volatile("cp.async.cg.shared.global [%0], [%1], 16;" :: "r"(s), "l"(g) : "memory");
}
#define LDSM4(r, a) \
    asm volatile("ldmatrix.sync.aligned.m8n8.x4.shared.b16 {%0,%1,%2,%3}, [%4];" \
        : "=r"((r)[0]), "=r"((r)[1]), "=r"((r)[2]), "=r"((r)[3]) : "r"(a))
#define MMA16816(c, a, b0, b1) \
    asm volatile("mma.sync.aligned.m16n8k16.row.col.f32.f16.f16.f32 " \
        "{%0,%1,%2,%3}, {%4,%5,%6,%7}, {%8,%9}, {%0,%1,%2,%3};" \
        : "+f"((c)[0]), "+f"((c)[1]), "+f"((c)[2]), "+f"((c)[3]) \
        : "r"((a)[0]), "r"((a)[1]), "r"((a)[2]), "r"((a)[3]), "r"(b0), "r"(b1))

__device__ __forceinline__ void gbar(int i, int n) {
    __syncthreads();
    if (threadIdx.x == 0) {
        __threadfence();
        atomicAdd(&d_bar[i], 1);
        while (atomicAdd(&d_bar[i], 0) < n) { __nanosleep(64); }
    }
    __syncthreads();
}

// ---------------- K0: zero scratch + detect index width ----------------
__global__ void k_zero(const void* eidx, const void* bat,
                       long long e2w, long long nw) {
    int idx = blockIdx.x * blockDim.x + threadIdx.x;
    int stride = gridDim.x * blockDim.x;
    for (int i = idx; i < MAXB * 128; i += stride) d_A[i] = 0.f;
    for (int i = idx; i < MAXB * 64;  i += stride) d_gx[i] = 0.f;
    for (int i = idx; i < MAXB;       i += stride) d_hist[i] = 0;
    for (int i = idx; i < 128;        i += stride) {
        d_Q[i] = 0.f; d_S1[i] = 0.f; d_Q1[i] = 0.f; d_S2[i] = 0.f; d_Q2[i] = 0.f;
    }
    if (idx < 8) d_bar[idx] = 0;
    if (blockIdx.x == 0 && threadIdx.x < 32) {
        const unsigned* we = (const unsigned*)eidx;
        const unsigned* wb = (const unsigned*)bat;
        int lane = threadIdx.x;
        int nz_e = 0, nz_b = 0;
        long long se = e2w / 64; if (se < 2) se = 2;
        long long sb = nw  / 64; if (sb < 2) sb = 2;
        for (int s = 0; s < 2; ++s) {
            long long k = lane * 2 + s;
            long long pe = (k * se) | 1; if (pe >= e2w) pe = 1;
            long long pb = (k * sb) | 1; if (pb >= nw)  pb = 1;
            if (we[pe] != 0u) nz_e++;
            if (wb[pb] != 0u) nz_b++;
        }
        for (int o = 16; o > 0; o >>= 1) {
            nz_e += __shfl_xor_sync(0xffffffffu, nz_e, o);
            nz_b += __shfl_xor_sync(0xffffffffu, nz_b, o);
        }
        if (lane == 0) {
            d_f_e64 = (nz_e < 8) ? 1 : 0;
            d_f_b64 = (nz_b < 8) ? 1 : 0;
        }
    }
}

// ---------------- K1: fused wprep + histogram + gx ----------------
__global__ void k_pre(const float* __restrict__ W1a,
                      const void* __restrict__ ei, const void* __restrict__ bat,
                      const float* __restrict__ x, long long E, long long N) {
    int tid = threadIdx.x, bid = blockIdx.x;
    long long gtid = (long long)bid * 256 + tid;
    int e64 = d_f_e64, b64 = d_f_b64;

    // wprep: W^T fp16 hi, padded rows (136)
    if (gtid < 16384) {
        int k = (int)(gtid >> 7), n = (int)(gtid & 127);
        __half h = __float2half(W1a[k * 128 + n]);
        d_Wt[n * 136 + k] = *(unsigned short*)&h;
    }

    // histogram: blocks 0..255, smem-privatized
    if (bid < 256) {
        __shared__ int lh[MAXB];
        for (int i = tid; i < MAXB; i += 256) lh[i] = 0;
        __syncthreads();
        long long stride = 256LL * 256;
        for (long long e = (long long)bid * 256 + tid; e < E; e += stride) {
            long long c = ldix(ei, E + e, e64);
            atomicAdd(&lh[(int)ldix(bat, c, b64)], 1);
        }
        __syncthreads();
        for (int i = tid; i < MAXB; i += 256)
            if (lh[i]) atomicAdd(&d_hist[i], lh[i]);
    }

    // gx: all blocks, strided over N*16 quads
    long long tot = N * 16;
    long long gstride = (long long)gridDim.x * 256;
    for (long long idx = gtid; idx < tot; idx += gstride) {
        long long node = idx >> 4;
        int q = (int)(idx & 15);
        int g = (int)ldix(bat, node, b64);
        float4 v = ((const float4*)x)[node * 16 + q];
        red4(d_gx + (long long)g * 64 + q * 4, v);
    }
}

// ---------------- sort pass 2: exclusive scan ----------------
__global__ void k_scan() {
    __shared__ int s[MAXB];
    int t = threadIdx.x;
    int v = d_hist[t];
    s[t] = v;
    __syncthreads();
    for (int o = 1; o < MAXB; o <<= 1) {
        int u = (t >= o) ? s[t - o] : 0;
        __syncthreads();
        s[t] += u;
        __syncthreads();
    }
    d_cur[t] = s[t] - v;
    d_cnt[t] = v;
}

// ---------------- sort pass 3: scatter (block-privatized cursors) ----------------
#define CH 4096
__global__ void k_scatter(const void* __restrict__ ei, const void* __restrict__ bat,
                          long long E) {
    __shared__ int sg_[CH], sr_[CH];
    __shared__ int lh[MAXB], lbase[MAXB];
    int tid = threadIdx.x;
    long long e0 = (long long)blockIdx.x * CH;
    for (int i = tid; i < MAXB; i += 256) lh[i] = 0;
    __syncthreads();
    int e64 = d_f_e64, b64 = d_f_b64;
    for (int i = tid; i < CH; i += 256) {
        long long e = e0 + i;
        if (e < E) {
            int r = (int)ldix(ei, e, e64);
            long long c = ldix(ei, E + e, e64);
            int g = (int)ldix(bat, c, b64);
            sr_[i] = r; sg_[i] = g;
            atomicAdd(&lh[g], 1);
        } else sg_[i] = -1;
    }
    __syncthreads();
    for (int g = tid; g < MAXB; g += 256)
        if (lh[g]) lbase[g] = atomicAdd(&d_cur[g], lh[g]);
    __syncthreads();
    for (int g = tid; g < MAXB; g += 256) lh[g] = 0;
    __syncthreads();
    for (int i = tid; i < CH; i += 256) {
        int g = sg_[i];
        if (g >= 0) {
            int o = atomicAdd(&lh[g], 1);
            d_se[lbase[g] + o] = make_int4(sr_[i], g, (int)(e0 + i), 0);
        }
    }
}

// ---------------- K2: persistent pipelined mma.sync edge kernel (sorted, fp16 2-prod) ----
__global__ __launch_bounds__(256, 1)
void k_edge(const float* __restrict__ x, const float* __restrict__ ea,
            const float* __restrict__ b1a, long long E, int ntiles) {
    extern __shared__ char smem[];
    const uint32_t sb = smem_u32(smem);
    const int tid = threadIdx.x, wid = tid >> 5, lane = tid & 31;
    const int wm = wid & 3, wn = wid >> 2;
    const int rowb = wm * 32, colb = wn * 64;

    // one-time: W tile (34.8KB)
    {
        const uint4* wsrc = (const uint4*)d_Wt;
        uint4* wdst = (uint4*)(smem + S_W);
        for (int i = tid; i < 2176; i += 256) wdst[i] = wsrc[i];
    }

    // bias for this lane's columns
    float bb0[8], bb1[8];
    #pragma unroll
    for (int ni = 0; ni < 8; ++ni) {
        int colp = colb + ni * 8 + 2 * (lane & 3);
        bb0[ni] = b1a[colp];
        bb1[ni] = b1a[colp + 1];
    }
    const int mycol = tid & 127, myhalf = tid >> 7;
    float qacc = 0.f;

    const int eSub = lane >> 4;
    const int c4   = lane & 15;
    const int arow = lane & 15;
    const int akof = (lane >> 4) * 16;
    const int brow = (lane & 7) + ((lane & 16) >> 1);
    const int bkof = ((lane >> 3) & 1) * 16;
    const int gstride = gridDim.x;

    // ---- prologue ----
    {
        long long e0 = (long long)blockIdx.x * 128;
        if (tid < 128) {
            long long e = e0 + tid;
            int4 v = (e < E) ? d_se[e] : make_int4(0, -1, 0, 0);
            *(int4*)(smem + S_IDX0 + tid * 16) = v;
        }
        __syncthreads();
        #pragma unroll
        for (int i = 0; i < 8; ++i) {
            int e = wid * 16 + i * 2 + eSub;
            int4 iv = *(const int4*)(smem + S_IDX0 + e * 16);
            cpa16(sb + S_RAW + (uint32_t)e * 528 + c4 * 16,       x + (size_t)iv.x * 64 + c4 * 4);
            cpa16(sb + S_RAW + (uint32_t)e * 528 + 256 + c4 * 16, ea + (size_t)iv.z * 64 + c4 * 4);
        }
        asm volatile("cp.async.commit_group;" ::: "memory");
    }

    for (int t = blockIdx.x; t < ntiles; t += gstride) {
        const int p = ((t / gstride) & 1);
        const uint32_t sip = (p ? S_IDX1 : S_IDX0);
        const uint32_t sin = (p ? S_IDX0 : S_IDX1);

        asm volatile("cp.async.wait_group 0;" ::: "memory");
        __syncthreads();                       // raw(t) ready; scan(t-1) done with S_A

        // ---- convert raw fp32 -> fp16 hi/lo ----
        #pragma unroll
        for (int i = 0; i < 8; ++i) {
            int e = wid * 16 + i * 2 + eSub;
            const char* rp = smem + S_RAW + (size_t)e * 528;
            char* ah = smem + S_A + (size_t)e * 272;
            char* al = ah + 34816;
            #pragma unroll
            for (int h = 0; h < 2; ++h) {
                float4 v = *(const float4*)(rp + h * 256 + c4 * 16);
                __half2 h01 = __floats2half2_rn(v.x, v.y);
                __half2 h23 = __floats2half2_rn(v.z, v.w);
                float2 f01 = __half22float2(h01);
                float2 f23 = __half22float2(h23);
                __half2 l01 = __floats2half2_rn(v.x - f01.x, v.y - f01.y);
                __half2 l23 = __floats2half2_rn(v.z - f23.x, v.w - f23.y);
                *(uint2*)(ah + h * 128 + c4 * 8) = make_uint2(*(uint32_t*)&h01, *(uint32_t*)&h23);
                *(uint2*)(al + h * 128 + c4 * 8) = make_uint2(*(uint32_t*)&l01, *(uint32_t*)&l23);
            }
        }

        // ---- indices for next tile ----
        const long long tn = (long long)t + gstride;
        const bool have_next = tn < ntiles;
        if (have_next && tid < 128) {
            long long e = tn * 128 + tid;
            int4 v = (e < E) ? d_se[e] : make_int4(0, -1, 0, 0);
            *(int4*)(smem + sin + tid * 16) = v;
        }
        __syncthreads();

        // ---- issue cp.async for next tile ----
        if (have_next) {
            #pragma unroll
            for (int i = 0; i < 8; ++i) {
                int e = wid * 16 + i * 2 + eSub;
                int4 iv = *(const int4*)(smem + sin + e * 16);
                cpa16(sb + S_RAW + (uint32_t)e * 528 + c4 * 16,       x + (size_t)iv.x * 64 + c4 * 4);
                cpa16(sb + S_RAW + (uint32_t)e * 528 + 256 + c4 * 16, ea + (size_t)iv.z * 64 + c4 * 4);
            }
            asm volatile("cp.async.commit_group;" ::: "memory");
        }

        // ---- MMA mainloop: 2 products (Ahi+Alo) x Whi ----
        float c[2][8][4];
        #pragma unroll
        for (int mi = 0; mi < 2; ++mi)
            #pragma unroll
            for (int ni = 0; ni < 8; ++ni)
                #pragma unroll
                for (int j = 0; j < 4; ++j) c[mi][ni][j] = 0.f;

        #pragma unroll
        for (int kk = 0; kk < 8; ++kk) {
            uint32_t ah[2][4], al_[2][4];
            #pragma unroll
            for (int mi = 0; mi < 2; ++mi) {
                uint32_t aaddr = sb + S_A + (uint32_t)(rowb + mi * 16 + arow) * 272
                                 + kk * 32 + akof;
                LDSM4(ah[mi], aaddr);
                LDSM4(al_[mi], aaddr + 34816u);
            }
            #pragma unroll
            for (int np = 0; np < 4; ++np) {
                uint32_t baddr = sb + S_W + (uint32_t)(colb + np * 16 + brow) * 272
                                 + kk * 32 + bkof;
                uint32_t bh[4];
                LDSM4(bh, baddr);
                #pragma unroll
                for (int mi = 0; mi < 2; ++mi) {
                    MMA16816(c[mi][np * 2 + 0], ah[mi],  bh[0], bh[1]);
                    MMA16816(c[mi][np * 2 + 1], ah[mi],  bh[2], bh[3]);
                    MMA16816(c[mi][np * 2 + 0], al_[mi], bh[0], bh[1]);
                    MMA16816(c[mi][np * 2 + 1], al_[mi], bh[2], bh[3]);
                }
            }
        }
        __syncthreads();                 // all warps done reading A fp16

        // ---- dump bias+leaky activations to smem (S_A as f32 [128][132]) ----
        float* dump = (float*)(smem + S_A);
        #pragma unroll
        for (int mi = 0; mi < 2; ++mi) {
            int rA = rowb + mi * 16 + (lane >> 2);
            int rB = rA + 8;
            #pragma unroll
            for (int ni = 0; ni < 8; ++ni) {
                int colp = colb + ni * 8 + 2 * (lane & 3);
                float2 vA = make_float2(leaky(c[mi][ni][0] + bb0[ni]),
                                        leaky(c[mi][ni][1] + bb1[ni]));
                float2 vB = make_float2(leaky(c[mi][ni][2] + bb0[ni]),
                                        leaky(c[mi][ni][3] + bb1[ni]));
                *(float2*)(dump + rA * 132 + colp) = vA;
                *(float2*)(dump + rB * 132 + colp) = vB;
            }
        }
        __syncthreads();

        // ---- column scan: sum 64 edges per (col, half); flush by graph ----
        int g0   = *(const int*)(smem + sip + 4);
        int g127 = *(const int*)(smem + sip + 127 * 16 + 4);
        bool mono = (g0 == g127) && (g0 >= 0);
        if (mono) {
            float acc = 0.f;
            const float* dp = dump + (myhalf * 64) * 132 + mycol;
            #pragma unroll 8
            for (int e = 0; e < 64; ++e) {
                float v = dp[e * 132];
                acc += v;
                qacc += v * v;
            }
            float* cb = (float*)(smem + S_CB);
            cb[myhalf * 128 + mycol] = acc;
            __syncthreads();
            if (tid < 128) cb[tid] = cb[tid] + cb[128 + tid];
            __syncthreads();
            if (tid < 32) {
                float4 vv = *(const float4*)((float*)(smem + S_CB) + tid * 4);
                red4(d_A + (size_t)g0 * 128 + tid * 4, vv);
            }
        } else {
            float acc = 0.f;
            int curg = -1;
            const float* dp = dump + (myhalf * 64) * 132 + mycol;
            const char* sgp = smem + sip + (myhalf * 64) * 16 + 4;
            for (int e = 0; e < 64; ++e) {
                int gg = *(const int*)(sgp + e * 16);
                float v = dp[e * 132];
                if (gg != curg) {
                    if (curg >= 0) redf(d_A + (size_t)curg * 128 + mycol, acc);
                    acc = 0.f;
                    curg = gg;
                }
                if (gg >= 0) { acc += v; qacc += v * v; }
            }
            if (curg >= 0) redf(d_A + (size_t)curg * 128 + mycol, acc);
        }
    }

    // ---- flush per-column Q ----
    atomicAdd(&d_Q[mycol], qacc);
}

// ---------------- fused tail: stats -> t2 -> g1 -> g2 -> g3 ----------------
__global__ void k_tail(const float* __restrict__ g1a, const float* __restrict__ be1a,
                       const float* __restrict__ b2a, const float* __restrict__ W2a,
                       const float* __restrict__ W1b, const float* __restrict__ b1b,
                       const float* __restrict__ W2b, const float* __restrict__ b2b,
                       const float* __restrict__ g1b, const float* __restrict__ be1b,
                       const float* __restrict__ W3b, const float* __restrict__ b3b,
                       const float* __restrict__ g2b, const float* __restrict__ be2b,
                       float Ef, float Bf, int B, int ngrid,
                       float* __restrict__ out) {
    __shared__ float sh1[128], sh2[128], sgx[64];
    int blk = blockIdx.x, tid = threadIdx.x;

    if (blk < 128) {
        float s = 0.f;
        for (int b = tid; b < B; b += 128) s += d_A[b * 128 + blk];
        sh1[tid] = s;
        __syncthreads();
        for (int o = 64; o; o >>= 1) {
            if (tid < o) sh1[tid] += sh1[tid + o];
            __syncthreads();
        }
        if (tid == 0) {
            float m = sh1[0] / Ef;
            float v = d_Q[blk] / Ef - m * m;
            float sc = g1a[blk] * rsqrtf(v + EPS);
            d_s1[blk] = sc;
            d_t1[blk] = be1a[blk] - m * sc;
        }
    }
    gbar(0, ngrid);

    if (blk < 128) {
        sh1[tid] = d_t1[tid] * W2a[tid * 128 + blk];
        __syncthreads();
        for (int o = 64; o; o >>= 1) {
            if (tid < o) sh1[tid] += sh1[tid + o];
            __syncthreads();
        }
        if (tid == 0) d_t2[blk] = sh1[0] + b2a[blk];
    }
    gbar(1, ngrid);

    if (blk < B) {
        int b = blk, j = tid;
        sh1[j] = d_A[b * 128 + j] * d_s1[j];
        if (j < 64) sgx[j] = d_gx[b * 64 + j];
        __syncthreads();
        float cf = (float)d_cnt[b];
        float ga = d_t2[j] * cf;
        #pragma unroll 8
        for (int k = 0; k < 128; ++k) ga += sh1[k] * W2a[k * 128 + j];
        sh2[j] = ga;
        __syncthreads();
        float z = b1b[j];
        #pragma unroll 8
        for (int i = 0; i < 64; ++i)  z += sgx[i] * W1b[i * 128 + j];
        #pragma unroll 8
        for (int i = 0; i < 128; ++i) z += sh2[i] * W1b[(64 + i) * 128 + j];
        float a = leaky(z);
        d_a1[b * 128 + j] = a;
        atomicAdd(&d_S1[j], a);
        atomicAdd(&d_Q1[j], a * a);
    }
    gbar(2, ngrid);

    if (blk < B) {
        int b = blk, j = tid;
        float m = d_S1[j] / Bf;
        float v = d_Q1[j] / Bf - m * m;
        float s = g1b[j] * rsqrtf(v + EPS);
        float tt = be1b[j] - m * s;
        sh1[j] = d_a1[b * 128 + j] * s + tt;
        __syncthreads();
        float z = b2b[j];
        #pragma unroll 8
        for (int k = 0; k < 128; ++k) z += sh1[k] * W2b[k * 128 + j];
        float a = leaky(z);
        d_a2[b * 128 + j] = a;
        atomicAdd(&d_S2[j], a);
        atomicAdd(&d_Q2[j], a * a);
        __syncthreads();
    }
    gbar(3, ngrid);

    if (blk < B) {
        int b = blk, j = tid;
        float m = d_S2[j] / Bf;
        float v = d_Q2[j] / Bf - m * m;
        float s = g2b[j] * rsqrtf(v + EPS);
        float tt = be2b[j] - m * s;
        sh1[j] = d_a2[b * 128 + j] * s + tt;
        __syncthreads();
        float z = b3b[j];
        #pragma unroll 8
        for (int k = 0; k < 128; ++k) z += sh1[k] * W3b[k * 128 + j];
        out[b * 128 + j] = z;
    }
}

// ---------------- launch ----------------
extern "C" void kernel_launch(void* const* d_in, const int* in_sizes, int n_in,
                              void* d_out, int out_size) {
    const float* x    = (const float*)d_in[0];
    const void*  ei   = d_in[1];
    const float* ea   = (const float*)d_in[2];
    const void*  bat  = d_in[4];
    const float* W1a  = (const float*)d_in[5];
    const float* b1a  = (const float*)d_in[6];
    const float* g1a  = (const float*)d_in[7];
    const float* be1a = (const float*)d_in[8];
    const float* W2a  = (const float*)d_in[9];
    const float* b2a  = (const float*)d_in[10];
    const float* W1b  = (const float*)d_in[11];
    const float* b1b  = (const float*)d_in[12];
    const float* g1b  = (const float*)d_in[13];
    const float* be1b = (const float*)d_in[14];
    const float* W2b  = (const float*)d_in[15];
    const float* b2b  = (const float*)d_in[16];
    const float* g2b  = (const float*)d_in[17];
    const float* be2b = (const float*)d_in[18];
    const float* W3b  = (const float*)d_in[19];
    const float* b3b  = (const float*)d_in[20];

    long long N = (long long)in_sizes[0] / 64;
    long long E = (long long)in_sizes[2] / 64;
    int B = in_sizes[3];
    if (B > MAXB) B = MAXB;

    static int smem_set = 0;
    if (!smem_set) {
        cudaFuncSetAttribute(k_edge, cudaFuncAttributeMaxDynamicSharedMemorySize, SMEM_TOT);
        smem_set = 1;
    }

    k_zero<<<256, 256>>>(ei, bat, 2 * E, N);

    int gridP = (int)((N * 16 + 255) / 256);
    if (gridP < 256) gridP = 256;
    k_pre<<<gridP, 256>>>(W1a, ei, bat, x, E, N);

    k_scan<<<1, MAXB>>>();
    int gridS = (int)((E + CH - 1) / CH);
    k_scatter<<<gridS, 256>>>(ei, bat, E);

    int ntiles = (int)((E + 127) / 128);
    int grid = ntiles < 148 ? ntiles : 148;
    k_edge<<<grid, 256, SMEM_TOT>>>(x, ea, b1a, E, ntiles);

    int ng = B > 128 ? B : 128;
    k_tail<<<ng, 128>>>(g1a, be1a, b2a, W2a, W1b, b1b, W2b, b2b, g1b, be1b,
                        W3b, b3b, g2b, be2b, (float)E, (float)B, B, ng,
                        (float*)d_out);
}